// round 12
// baseline (speedup 1.0000x reference)
#include <cuda_runtime.h>
#include <cuda_bf16.h>

// ---------------- dims ----------------
#define BD 4
#define TD 16384
#define BT (BD * TD)     // 65536 time-batch columns
#define RCD 32
#define DCD 32
#define SCD 256
#define NCLS 256
#define NCOND 80
#define NLAY 40

// main kernel tiling: 512 threads, single wave (140 blocks)
#define NT1 512
#define HALO 40
#define TILE1 472
#define NTILES 35

// packed per-layer weight layout (float offsets) -- conditioning on tensor path
#define OFF_FW0 0
#define OFF_FW1 1024
#define OFF_GW0 2048
#define OFF_GW1 3072
#define OFF_OW  4096
#define WPL     5120

// end kernel tiling
#define TT2 128
#define NT2 512

// cond GEMM (mma.sync bf16): K = 240 (Whi|Whi|Wlo  x  hhi|hlo|hhi), 15 k-steps
#define CK 240
#define NKS 15
#define SPH 248          // bf16 row stride for hs/ws (stride%32 words = 28 -> conflict-free)

// ---------------- device scratch (static, no allocation) ----------------
__device__ float g_wpack[NLAY * WPL];             // packed layer weights (conv+out)
__device__ __nv_bfloat16 g_wb[2560 * 256];        // cond weights bf16 split, K-concat (stride 256)
__device__ float g_e1[RCD * SCD];
__device__ float g_e2[SCD * NCLS];
__device__ float g_skips[BD * RCD * TD];          // 8 MB skip buffer
__device__ unsigned long long g_z[1280ull * BT];  // 671 MB cond pre-activations (f32 pairs)

// ---------------- f32x2 helpers ----------------
typedef unsigned long long u64;
typedef unsigned int u32;

__device__ __forceinline__ u64 pk2(float v) {
    u64 r;
    asm("mov.b64 %0, {%1, %2};" : "=l"(r) : "f"(v), "f"(v));
    return r;
}
__device__ __forceinline__ u64 pk2u(u32 lo, u32 hi) {
    u64 r;
    asm("mov.b64 %0, {%1, %2};" : "=l"(r) : "r"(lo), "r"(hi));
    return r;
}
__device__ __forceinline__ void fma2(u64 &d, u64 a, u64 b) {
    asm("fma.rn.f32x2 %0, %1, %2, %0;" : "+l"(d) : "l"(a), "l"(b));
}
__device__ __forceinline__ float2 upk(u64 v) {
    float2 r;
    asm("mov.b64 {%0, %1}, %2;" : "=f"(r.x), "=f"(r.y) : "l"(v));
    return r;
}

__device__ __forceinline__ float fast_tanh(float x) {
    float a = fminf(fmaxf(-2.f * x, -60.f), 60.f);
    float e = __expf(a);
    return (1.f - e) * __fdividef(1.f, 1.f + e);
}
__device__ __forceinline__ float fast_sig(float x) {
    float a = fminf(fmaxf(-x, -60.f), 60.f);
    float e = __expf(a);
    return __fdividef(1.f, 1.f + e);
}

// warp-level bf16 MMA: D(16x8,f32) += A(16x16,row) * B(16x8,col)
__device__ __forceinline__ void mma16816(float* c, const u32* a, const u32* b) {
    asm volatile(
        "mma.sync.aligned.m16n8k16.row.col.f32.bf16.bf16.f32 "
        "{%0,%1,%2,%3}, {%4,%5,%6,%7}, {%8,%9}, {%0,%1,%2,%3};"
        : "+f"(c[0]), "+f"(c[1]), "+f"(c[2]), "+f"(c[3])
        : "r"(a[0]), "r"(a[1]), "r"(a[2]), "r"(a[3]), "r"(b[0]), "r"(b[1]));
}

// ---------------- weight repack + compose kernel ----------------
__global__ void wn_pack(const float* __restrict__ dil_w, const float* __restrict__ f_w,
                        const float* __restrict__ g_w,   const float* __restrict__ cf_w,
                        const float* __restrict__ cg_w,  const float* __restrict__ out_w,
                        const float* __restrict__ e1_w,  const float* __restrict__ e2_w) {
    int stride = gridDim.x * blockDim.x;
    int tid0 = blockIdx.x * blockDim.x + threadIdx.x;

    for (int i = tid0; i < NLAY * WPL; i += stride) {
        int l = i / WPL, off = i % WPL;
        float v;
        if (off < 4096) {
            int which = off >> 10;
            int o = off & 1023;
            int c = o >> 5, ch = o & 31;
            int k = which & 1;
            const float* base = (which < 2) ? f_w : g_w;
            float s = 0.f;
            #pragma unroll 8
            for (int d = 0; d < 32; ++d)
                s += base[(l * 32 + ch) * 32 + d] * dil_w[((l * 32 + d) * 32 + c) * 2 + k];
            v = s;
        } else {                                      // OW packed [d][r]
            int o = off - 4096; int c = o >> 5, r = o & 31;
            v = out_w[(l * 32 + r) * 32 + c];
        }
        g_wpack[i] = v;
    }
    // cond weights bf16-split K-concat: row r = l*64 + (ch<32 ? CF ch : CG ch-32)
    for (int j = tid0; j < 2560 * 256; j += stride) {
        int r = j >> 8, k = j & 255;
        int l = r >> 6, ch = r & 63;
        const float* src = (ch < 32) ? cf_w + (l * 32 + ch) * NCOND
                                     : cg_w + (l * 32 + (ch - 32)) * NCOND;
        __nv_bfloat16 o;
        if (k < 80) {
            o = __float2bfloat16(src[k]);                                 // Whi (x hhi)
        } else if (k < 160) {
            o = __float2bfloat16(src[k - 80]);                            // Whi (x hlo)
        } else if (k < 240) {
            float w = src[k - 160];
            __nv_bfloat16 hi = __float2bfloat16(w);
            o = __float2bfloat16(w - __bfloat162float(hi));               // Wlo (x hhi)
        } else {
            o = __float2bfloat16(0.f);
        }
        g_wb[j] = o;
    }
    for (int j = tid0; j < RCD * SCD; j += stride) {
        int c = j >> 8, s = j & 255;
        g_e1[j] = e1_w[s * RCD + c];
    }
    for (int j = tid0; j < SCD * NCLS; j += stride) {
        int c = j >> 8, s = j & 255;
        g_e2[j] = e2_w[s * SCD + c];
    }
}

// ---------------- cond GEMM: Z = Wc @ h, bf16-split on mma.sync ----------------
// grid (512, 20): x -> 128-time tile (b folded), y -> 128-channel tile. 256 threads.
// smem: hs[128][SPH] bf16 (63488 B), ws[128][SPH] bf16 (63488 B), fbuf[80][129] f32 (41280 B)
#define HS_OFF 0
#define WS_OFF (128 * SPH * 2)
#define FB_OFF (2 * 128 * SPH * 2)
#define CSM2   (FB_OFF + 80 * 129 * 4)

__global__ void __launch_bounds__(256, 1)
wn_cond(const float* __restrict__ h) {
    extern __shared__ char csm[];
    __nv_bfloat16* hs = (__nv_bfloat16*)(csm + HS_OFF);
    __nv_bfloat16* ws = (__nv_bfloat16*)(csm + WS_OFF);
    float* fbuf = (float*)(csm + FB_OFF);

    const int tid = threadIdx.x;
    const int b = blockIdx.x >> 7;                 // TD/128 = 128 time tiles per batch
    const int t0 = (blockIdx.x & 127) << 7;
    const int ch0 = blockIdx.y << 7;

    // phase 1a: coalesced h tile -> fbuf[c][t] (stride 129: conflict-free both ways)
    #pragma unroll 1
    for (int idx = tid; idx < NCOND * 128; idx += 256) {
        int c = idx >> 7, t = idx & 127;
        fbuf[c * 129 + t] = h[(b * NCOND + c) * TD + t0 + t];
    }
    // phase 1b: weight tile g_wb -> ws rows (uint4 chunks, 240 bf16 of 256 per row)
    #pragma unroll 1
    for (int idx = tid; idx < 128 * 30; idx += 256) {
        int r = idx / 30, ck = idx % 30;
        *(uint4*)((char*)ws + r * (SPH * 2) + ck * 16) =
            *(const uint4*)(g_wb + (ch0 + r) * 256 + ck * 8);
    }
    __syncthreads();

    // phase 2: transpose-convert fbuf -> hs[t][k] (k<80 hhi, 80..159 hlo, 160..239 hhi)
    #pragma unroll 1
    for (int idx = tid; idx < NCOND * 128; idx += 256) {
        int t = idx / NCOND, c = idx % NCOND;
        float hv = fbuf[c * 129 + t];
        __nv_bfloat16 hi = __float2bfloat16(hv);
        __nv_bfloat16 lo = __float2bfloat16(hv - __bfloat162float(hi));
        __nv_bfloat16* row = hs + t * SPH;
        row[c] = hi;
        row[c + 80] = lo;
        row[c + 160] = hi;
    }
    __syncthreads();

    // warp tiling: 8 warps = 4 time-groups x 2 ch-groups; warp = 32t x 64ch
    const int wid = tid >> 5, lane = tid & 31;
    const int tg = wid >> 1, cg = wid & 1;
    const int g = lane >> 2, tig = lane & 3;

    float acc[2][8][4];
    #pragma unroll
    for (int mi = 0; mi < 2; ++mi)
        #pragma unroll
        for (int ni = 0; ni < 8; ++ni)
            #pragma unroll
            for (int j = 0; j < 4; ++j) acc[mi][ni][j] = 0.f;

    #pragma unroll 1
    for (int kc = 0; kc < NKS; ++kc) {
        const int k16 = kc * 16;
        u32 a[2][4];
        #pragma unroll
        for (int mi = 0; mi < 2; ++mi) {
            const int tr = tg * 32 + mi * 16 + g;
            const __nv_bfloat16* r0 = hs + tr * SPH + k16 + tig * 2;
            const __nv_bfloat16* r1 = hs + (tr + 8) * SPH + k16 + tig * 2;
            a[mi][0] = *(const u32*)r0;
            a[mi][1] = *(const u32*)r1;
            a[mi][2] = *(const u32*)(r0 + 8);
            a[mi][3] = *(const u32*)(r1 + 8);
        }
        u32 bb[8][2];
        #pragma unroll
        for (int ni = 0; ni < 8; ++ni) {
            const int ch = cg * 64 + ni * 8 + g;
            const __nv_bfloat16* wr = ws + ch * SPH + k16 + tig * 2;
            bb[ni][0] = *(const u32*)wr;
            bb[ni][1] = *(const u32*)(wr + 8);
        }
        #pragma unroll
        for (int mi = 0; mi < 2; ++mi)
            #pragma unroll
            for (int ni = 0; ni < 8; ++ni)
                mma16816(acc[mi][ni], a[mi], bb[ni]);
    }

    // epilogue: D[t][ch], (c0,c1)/(c2,c3) are adjacent channel pairs -> u64 stores
    const u64 colb = (u64)blockIdx.x * 128 + tg * 32 + g;
    #pragma unroll
    for (int mi = 0; mi < 2; ++mi) {
        #pragma unroll
        for (int ni = 0; ni < 8; ++ni) {
            const int rp = ((ch0 + cg * 64 + ni * 8) >> 1) + tig;
            const u64 c0 = colb + mi * 16;
            g_z[(u64)rp * BT + c0]     = pk2u(__float_as_uint(acc[mi][ni][0]),
                                              __float_as_uint(acc[mi][ni][1]));
            g_z[(u64)rp * BT + c0 + 8] = pk2u(__float_as_uint(acc[mi][ni][2]),
                                              __float_as_uint(acc[mi][ni][3]));
        }
    }
}

// ---------------- fused 40-layer WaveNet body ----------------
#define SM1_FLOATS (2 * RCD * (NT1 + 1) + 2 * WPL)
#define SM1_BYTES  (SM1_FLOATS * 4)

__global__ void __launch_bounds__(NT1, 1)
wn_main(const float* __restrict__ x, const float* __restrict__ start_w) {
    extern __shared__ float sm[];
    float* res0 = sm;
    float* res1 = res0 + RCD * (NT1 + 1);
    float* w0s  = res1 + RCD * (NT1 + 1);
    float* w1s  = w0s + WPL;

    const int tid = threadIdx.x;
    const int b = blockIdx.y;
    const int t = blockIdx.x * TILE1 - HALO + tid;
    const bool tin = (t >= 0) && (t < TD);
    const int col = b * TD + (tin ? t : 0);

    if (tid < RCD) {
        res0[tid * (NT1 + 1)] = 0.f;
        res1[tid * (NT1 + 1)] = 0.f;
    }

    const float xv = tin ? x[b * TD + t] : 0.f;
    #pragma unroll
    for (int c = 0; c < RCD; ++c)
        res0[c * (NT1 + 1) + tid + 1] = start_w[c] * xv;

    #pragma unroll 1
    for (int i = tid; i < WPL / 4; i += NT1)
        ((float4*)w0s)[i] = ((const float4*)g_wpack)[i];

    for (int l = 0; l < NLAY; ++l) {
        __syncthreads();   // the ONLY barrier per layer

        const int cur = l & 1;
        const float* rc = cur ? res1 : res0;
        float*       rn = cur ? res0 : res1;
        const float* wc = cur ? w1s  : w0s;
        float*       wp = cur ? w0s  : w1s;

        if (l + 1 < NLAY) {
            const float4* src = (const float4*)(g_wpack + (l + 1) * WPL);
            #pragma unroll 1
            for (int i = tid; i < WPL / 4; i += NT1) ((float4*)wp)[i] = src[i];
        }

        // ---- init accumulators from precomputed conditioning Z ----
        u64 f2[16], g2[16];
        if (tin) {
            const u64* zf = g_z + (u64)(l * 32) * BT + col;
            #pragma unroll
            for (int p = 0; p < 16; ++p) f2[p] = zf[(u64)p * BT];
            const u64* zg = g_z + (u64)(l * 32 + 16) * BT + col;
            #pragma unroll
            for (int p = 0; p < 16; ++p) g2[p] = zg[(u64)p * BT];
        } else {
            #pragma unroll
            for (int p = 0; p < 16; ++p) { f2[p] = 0ull; g2[p] = 0ull; }
        }

        // ---- conv (folded) filter part ----
        #pragma unroll 4
        for (int c = 0; c < RCD; ++c) {
            u64 vn2 = pk2(rc[c * (NT1 + 1) + tid]);
            u64 vc2 = pk2(rc[c * (NT1 + 1) + tid + 1]);
            const ulonglong2* a0 = (const ulonglong2*)(wc + OFF_FW0 + c * 32);
            const ulonglong2* a1 = (const ulonglong2*)(wc + OFF_FW1 + c * 32);
            #pragma unroll
            for (int q = 0; q < 8; ++q) {
                ulonglong2 w0 = a0[q], w1 = a1[q];
                fma2(f2[2 * q], w0.x, vn2); fma2(f2[2 * q + 1], w0.y, vn2);
                fma2(f2[2 * q], w1.x, vc2); fma2(f2[2 * q + 1], w1.y, vc2);
            }
        }
        float filt[32];
        #pragma unroll
        for (int p = 0; p < 16; ++p) {
            float2 v = upk(f2[p]);
            filt[2 * p]     = fast_tanh(v.x);
            filt[2 * p + 1] = fast_tanh(v.y);
        }

        // ---- conv (folded) gate part ----
        #pragma unroll 4
        for (int c = 0; c < RCD; ++c) {
            u64 vn2 = pk2(rc[c * (NT1 + 1) + tid]);
            u64 vc2 = pk2(rc[c * (NT1 + 1) + tid + 1]);
            const ulonglong2* a0 = (const ulonglong2*)(wc + OFF_GW0 + c * 32);
            const ulonglong2* a1 = (const ulonglong2*)(wc + OFF_GW1 + c * 32);
            #pragma unroll
            for (int q = 0; q < 8; ++q) {
                ulonglong2 w0 = a0[q], w1 = a1[q];
                fma2(g2[2 * q], w0.x, vn2); fma2(g2[2 * q + 1], w0.y, vn2);
                fma2(g2[2 * q], w1.x, vc2); fma2(g2[2 * q + 1], w1.y, vc2);
            }
        }
        #pragma unroll
        for (int p = 0; p < 16; ++p) {
            float2 v = upk(g2[p]);
            filt[2 * p]     *= fast_sig(v.x);
            filt[2 * p + 1] *= fast_sig(v.y);
        }

        // ---- out = OW @ fg ; residual -> next buffer ----
        u64 o2[16];
        #pragma unroll
        for (int p = 0; p < 16; ++p) o2[p] = 0ull;
        #pragma unroll
        for (int c = 0; c < DCD; ++c) {
            u64 v2 = pk2(filt[c]);
            const ulonglong2* a = (const ulonglong2*)(wc + OFF_OW + c * 32);
            #pragma unroll
            for (int q = 0; q < 8; ++q) {
                ulonglong2 w = a[q];
                fma2(o2[2 * q], w.x, v2); fma2(o2[2 * q + 1], w.y, v2);
            }
        }
        #pragma unroll
        for (int p = 0; p < 16; ++p) {
            float2 o = upk(o2[p]);
            rn[(2 * p) * (NT1 + 1) + tid + 1]     = rc[(2 * p) * (NT1 + 1) + tid + 1] + o.x;
            rn[(2 * p + 1) * (NT1 + 1) + tid + 1] = rc[(2 * p + 1) * (NT1 + 1) + tid + 1] + o.y;
        }
    }

    if (tid >= HALO && t < TD) {
        #pragma unroll
        for (int c = 0; c < RCD; ++c)
            g_skips[(b * RCD + c) * TD + t] =
                res0[c * (NT1 + 1) + tid + 1] - start_w[c] * xv;
    }
}

// ---------------- end stack: relu -> 256x32 -> relu -> 256x256 ----------------
#define SM2_FLOATS (SCD * TT2 + RCD * NCLS + RCD * TT2)
#define SM2_BYTES  (SM2_FLOATS * 4)

__global__ void __launch_bounds__(NT2, 1)
wn_end(float* __restrict__ out) {
    extern __shared__ float sm[];
    float* e_s = sm;                       // [256][TT2]
    float* w_s = e_s + SCD * TT2;          // [8192]
    float* s_s = w_s + RCD * NCLS;         // [32][TT2]

    const int tid = threadIdx.x;
    const int b = blockIdx.y;
    const int t0 = blockIdx.x * TT2;
    const int g = tid >> 7;
    const int tc = tid & 127;
    const int t = t0 + tc;

    #pragma unroll 1
    for (int i = tid; i < RCD * SCD; i += NT2) w_s[i] = g_e1[i];
    #pragma unroll 1
    for (int i = tid; i < RCD * TT2; i += NT2) {
        int c = i >> 7, tt = i & 127;
        s_s[i] = fmaxf(g_skips[(b * RCD + c) * TD + t0 + tt], 0.f);
    }
    __syncthreads();

    u64 acc[32];
    #pragma unroll
    for (int p = 0; p < 32; ++p) acc[p] = 0ull;
    #pragma unroll 2
    for (int c = 0; c < RCD; ++c) {
        u64 v2 = pk2(s_s[c * TT2 + tc]);
        const ulonglong2* wr = (const ulonglong2*)(w_s + c * SCD + (g << 6));
        #pragma unroll
        for (int q = 0; q < 16; ++q) {
            ulonglong2 a = wr[q];
            fma2(acc[2 * q], a.x, v2); fma2(acc[2 * q + 1], a.y, v2);
        }
    }
    #pragma unroll
    for (int p = 0; p < 32; ++p) {
        float2 v = upk(acc[p]);
        int sc = (g << 6) + 2 * p;
        e_s[sc * TT2 + tc]       = fmaxf(v.x, 0.f);
        e_s[(sc + 1) * TT2 + tc] = fmaxf(v.y, 0.f);
    }

    #pragma unroll
    for (int p = 0; p < 32; ++p) acc[p] = 0ull;
    for (int kk = 0; kk < SCD / RCD; ++kk) {
        __syncthreads();
        #pragma unroll 1
        for (int i = tid; i < RCD * NCLS; i += NT2) w_s[i] = g_e2[kk * RCD * NCLS + i];
        __syncthreads();
        #pragma unroll 2
        for (int c = 0; c < RCD; ++c) {
            u64 v2 = pk2(e_s[(kk * RCD + c) * TT2 + tc]);
            const ulonglong2* wr = (const ulonglong2*)(w_s + c * NCLS + (g << 6));
            #pragma unroll
            for (int q = 0; q < 16; ++q) {
                ulonglong2 a = wr[q];
                fma2(acc[2 * q], a.x, v2); fma2(acc[2 * q + 1], a.y, v2);
            }
        }
    }
    #pragma unroll
    for (int p = 0; p < 32; ++p) {
        float2 v = upk(acc[p]);
        int cls = (g << 6) + 2 * p;
        out[(b * NCLS + cls) * TD + t]       = v.x;
        out[(b * NCLS + cls + 1) * TD + t]   = v.y;
    }
}

// ---------------- launch ----------------
extern "C" void kernel_launch(void* const* d_in, const int* in_sizes, int n_in,
                              void* d_out, int out_size) {
    const float* x       = (const float*)d_in[0];
    const float* h       = (const float*)d_in[1];
    const float* start_w = (const float*)d_in[2];
    const float* dil_w   = (const float*)d_in[3];
    const float* f_w     = (const float*)d_in[4];
    const float* g_w     = (const float*)d_in[5];
    const float* cf_w    = (const float*)d_in[6];
    const float* cg_w    = (const float*)d_in[7];
    const float* out_w   = (const float*)d_in[8];
    const float* e1_w    = (const float*)d_in[9];
    const float* e2_w    = (const float*)d_in[10];
    float* out = (float*)d_out;

    cudaFuncSetAttribute(wn_cond, cudaFuncAttributeMaxDynamicSharedMemorySize, CSM2);
    cudaFuncSetAttribute(wn_main, cudaFuncAttributeMaxDynamicSharedMemorySize, SM1_BYTES);
    cudaFuncSetAttribute(wn_end,  cudaFuncAttributeMaxDynamicSharedMemorySize, SM2_BYTES);

    wn_pack<<<256, 256>>>(dil_w, f_w, g_w, cf_w, cg_w, out_w, e1_w, e2_w);
    wn_cond<<<dim3(512, 20), 256, CSM2>>>(h);
    wn_main<<<dim3(NTILES, BD), NT1, SM1_BYTES>>>(x, start_w);
    wn_end<<<dim3(TD / TT2, BD), NT2, SM2_BYTES>>>(out);
}

// round 13
// speedup vs baseline: 1.4038x; 1.4038x over previous
#include <cuda_runtime.h>
#include <cuda_bf16.h>

// ---------------- dims ----------------
#define BD 4
#define TD 16384
#define BT (BD * TD)     // 65536 time-batch columns
#define RCD 32
#define DCD 32
#define SCD 256
#define NCLS 256
#define NCOND 80
#define NLAY 40

// main kernel tiling: 512 threads, single wave (140 blocks)
#define NT1 512
#define HALO 40
#define TILE1 472
#define NTILES 35

// packed per-layer weight layout (float offsets) -- conditioning on tensor path
#define OFF_FW0 0
#define OFF_FW1 1024
#define OFF_GW0 2048
#define OFF_GW1 3072
#define OFF_OW  4096
#define WPL     5120

// end kernel tiling
#define TT2 128
#define NT2 512

// cond GEMM (mma.sync bf16): K = 240 (Whi|Whi|Wlo  x  hhi|hlo|hhi), 15 k-steps
#define CK 240
#define NKS 15
#define SPH 248          // bf16 row stride (words%32 = 28 -> conflict-free)
#define NCHT 20          // 2560 channels / 128 per tile

// ---------------- device scratch (static, no allocation) ----------------
__device__ float g_wpack[NLAY * WPL];
__device__ __align__(16) __nv_bfloat16 g_wb[2560 * 256];  // cond weights bf16 split
__device__ float g_e1[RCD * SCD];
__device__ float g_e2[SCD * NCLS];
__device__ float g_skips[BD * RCD * TD];
__device__ unsigned long long g_z[1280ull * BT];          // cond pre-activations (f32 pairs)

// ---------------- helpers ----------------
typedef unsigned long long u64;
typedef unsigned int u32;

__device__ __forceinline__ u64 pk2(float v) {
    u64 r;
    asm("mov.b64 %0, {%1, %2};" : "=l"(r) : "f"(v), "f"(v));
    return r;
}
__device__ __forceinline__ u64 pk2u(u32 lo, u32 hi) {
    u64 r;
    asm("mov.b64 %0, {%1, %2};" : "=l"(r) : "r"(lo), "r"(hi));
    return r;
}
__device__ __forceinline__ void fma2(u64 &d, u64 a, u64 b) {
    asm("fma.rn.f32x2 %0, %1, %2, %0;" : "+l"(d) : "l"(a), "l"(b));
}
__device__ __forceinline__ float2 upk(u64 v) {
    float2 r;
    asm("mov.b64 {%0, %1}, %2;" : "=f"(r.x), "=f"(r.y) : "l"(v));
    return r;
}
__device__ __forceinline__ u32 smem_u32(const void* p) {
    u32 a;
    asm("{ .reg .u64 t; cvta.to.shared.u64 t, %1; cvt.u32.u64 %0, t; }" : "=r"(a) : "l"(p));
    return a;
}

__device__ __forceinline__ float fast_tanh(float x) {
    float a = fminf(fmaxf(-2.f * x, -60.f), 60.f);
    float e = __expf(a);
    return (1.f - e) * __fdividef(1.f, 1.f + e);
}
__device__ __forceinline__ float fast_sig(float x) {
    float a = fminf(fmaxf(-x, -60.f), 60.f);
    float e = __expf(a);
    return __fdividef(1.f, 1.f + e);
}

// warp-level bf16 MMA: D(16x8,f32) += A(16x16,row) * B(16x8,col)
__device__ __forceinline__ void mma16816(float* c, const u32* a, const u32* b) {
    asm volatile(
        "mma.sync.aligned.m16n8k16.row.col.f32.bf16.bf16.f32 "
        "{%0,%1,%2,%3}, {%4,%5,%6,%7}, {%8,%9}, {%0,%1,%2,%3};"
        : "+f"(c[0]), "+f"(c[1]), "+f"(c[2]), "+f"(c[3])
        : "r"(a[0]), "r"(a[1]), "r"(a[2]), "r"(a[3]), "r"(b[0]), "r"(b[1]));
}

// ---------------- weight repack + compose kernel ----------------
__global__ void wn_pack(const float* __restrict__ dil_w, const float* __restrict__ f_w,
                        const float* __restrict__ g_w,   const float* __restrict__ cf_w,
                        const float* __restrict__ cg_w,  const float* __restrict__ out_w,
                        const float* __restrict__ e1_w,  const float* __restrict__ e2_w) {
    int stride = gridDim.x * blockDim.x;
    int tid0 = blockIdx.x * blockDim.x + threadIdx.x;

    for (int i = tid0; i < NLAY * WPL; i += stride) {
        int l = i / WPL, off = i % WPL;
        float v;
        if (off < 4096) {
            int which = off >> 10;
            int o = off & 1023;
            int c = o >> 5, ch = o & 31;
            int k = which & 1;
            const float* base = (which < 2) ? f_w : g_w;
            float s = 0.f;
            #pragma unroll 8
            for (int d = 0; d < 32; ++d)
                s += base[(l * 32 + ch) * 32 + d] * dil_w[((l * 32 + d) * 32 + c) * 2 + k];
            v = s;
        } else {                                      // OW packed [d][r]
            int o = off - 4096; int c = o >> 5, r = o & 31;
            v = out_w[(l * 32 + r) * 32 + c];
        }
        g_wpack[i] = v;
    }
    // cond weights bf16-split K-concat: row r = l*64 + (ch<32 ? CF ch : CG ch-32)
    for (int j = tid0; j < 2560 * 256; j += stride) {
        int r = j >> 8, k = j & 255;
        int l = r >> 6, ch = r & 63;
        const float* src = (ch < 32) ? cf_w + (l * 32 + ch) * NCOND
                                     : cg_w + (l * 32 + (ch - 32)) * NCOND;
        __nv_bfloat16 o;
        if (k < 80) {
            o = __float2bfloat16(src[k]);                                 // Whi (x hhi)
        } else if (k < 160) {
            o = __float2bfloat16(src[k - 80]);                            // Whi (x hlo)
        } else if (k < 240) {
            float w = src[k - 160];
            __nv_bfloat16 hi = __float2bfloat16(w);
            o = __float2bfloat16(w - __bfloat162float(hi));               // Wlo (x hhi)
        } else {
            o = __float2bfloat16(0.f);
        }
        g_wb[j] = o;
    }
    for (int j = tid0; j < RCD * SCD; j += stride) {
        int c = j >> 8, s = j & 255;
        g_e1[j] = e1_w[s * RCD + c];
    }
    for (int j = tid0; j < SCD * NCLS; j += stride) {
        int c = j >> 8, s = j & 255;
        g_e2[j] = e2_w[s * SCD + c];
    }
}

// ---------------- cond GEMM: Z = Wc @ h, bf16-split mma.sync ----------------
// grid (512): one block per 128-time tile; block loops over all 20 channel tiles.
// smem: hs[128][SPH] bf16, ws double buffer 2x[128][SPH] bf16; fbuf overlaps wsA.
#define HS_OFF  0
#define WSA_OFF (128 * SPH * 2)                 // 63488
#define WSB_OFF (WSA_OFF + 128 * SPH * 2)       // 126976
#define FB_OFF  WSA_OFF                         // fbuf (41280 B) reuses wsA pre-loop
#define CSM2    (WSB_OFF + 128 * SPH * 2)       // 190464 B

__global__ void __launch_bounds__(256, 1)
wn_cond(const float* __restrict__ h) {
    extern __shared__ char csm[];
    __nv_bfloat16* hs = (__nv_bfloat16*)(csm + HS_OFF);
    float* fbuf = (float*)(csm + FB_OFF);

    const int tid = threadIdx.x;
    const int b = blockIdx.x >> 7;
    const int t0 = (blockIdx.x & 127) << 7;

    // phase 1: coalesced h tile -> fbuf[c][t] (stride 129: conflict-free both ways)
    #pragma unroll 1
    for (int idx = tid; idx < NCOND * 128; idx += 256) {
        int c = idx >> 7, t = idx & 127;
        fbuf[c * 129 + t] = h[(b * NCOND + c) * TD + t0 + t];
    }
    __syncthreads();
    // phase 2: transpose-convert fbuf -> hs[t][k] (k<80 hhi, 80..159 hlo, 160..239 hhi)
    #pragma unroll 1
    for (int idx = tid; idx < NCOND * 128; idx += 256) {
        int t = idx / NCOND, c = idx % NCOND;
        float hv = fbuf[c * 129 + t];
        __nv_bfloat16 hi = __float2bfloat16(hv);
        __nv_bfloat16 lo = __float2bfloat16(hv - __bfloat162float(hi));
        __nv_bfloat16* row = hs + t * SPH;
        row[c] = hi;
        row[c + 80] = lo;
        row[c + 160] = hi;
    }
    __syncthreads();   // fbuf (wsA region) free from here

    const u32 ws_s[2] = { smem_u32(csm + WSA_OFF), smem_u32(csm + WSB_OFF) };

    // prefill ws buffer 0 with channel-tile 0 (15 x 16B cp.async per thread)
    {
        const char* srcb = (const char*)g_wb;
        #pragma unroll 1
        for (int i2 = 0; i2 < 15; ++i2) {
            int idx = tid + i2 * 256;
            int r = idx / 30, ck = idx % 30;
            u32 d = ws_s[0] + r * (SPH * 2) + ck * 16;
            asm volatile("cp.async.ca.shared.global [%0], [%1], 16;"
                         :: "r"(d), "l"(srcb + (r * 256 + ck * 8) * 2) : "memory");
        }
        asm volatile("cp.async.commit_group;" ::: "memory");
    }

    const int wid = tid >> 5, lane = tid & 31;
    const int tg = wid >> 1, cg = wid & 1;
    const int g = lane >> 2, tig = lane & 3;
    const u64 colb = (u64)blockIdx.x * 128 + tg * 32 + g;

    #pragma unroll 1
    for (int nc = 0; nc < NCHT; ++nc) {
        const int cur = nc & 1;
        __syncthreads();   // prior iteration's reads of buf[cur^1] complete

        if (nc + 1 < NCHT) {      // prefetch next channel tile into the idle buffer
            const char* srcb = (const char*)(g_wb + (u64)(nc + 1) * 128 * 256);
            #pragma unroll 1
            for (int i2 = 0; i2 < 15; ++i2) {
                int idx = tid + i2 * 256;
                int r = idx / 30, ck = idx % 30;
                u32 d = ws_s[cur ^ 1] + r * (SPH * 2) + ck * 16;
                asm volatile("cp.async.ca.shared.global [%0], [%1], 16;"
                             :: "r"(d), "l"(srcb + (r * 256 + ck * 8) * 2) : "memory");
            }
            asm volatile("cp.async.commit_group;" ::: "memory");
            asm volatile("cp.async.wait_group 1;" ::: "memory");
        } else {
            asm volatile("cp.async.wait_group 0;" ::: "memory");
        }
        __syncthreads();   // buf[cur] visible to all threads

        const __nv_bfloat16* ws = (const __nv_bfloat16*)(csm + (cur ? WSB_OFF : WSA_OFF));
        const int ch0 = nc * 128;

        float acc[2][8][4];
        #pragma unroll
        for (int mi = 0; mi < 2; ++mi)
            #pragma unroll
            for (int ni = 0; ni < 8; ++ni)
                #pragma unroll
                for (int j = 0; j < 4; ++j) acc[mi][ni][j] = 0.f;

        #pragma unroll 1
        for (int kc = 0; kc < NKS; ++kc) {
            const int k16 = kc * 16;
            u32 a[2][4];
            #pragma unroll
            for (int mi = 0; mi < 2; ++mi) {
                const int tr = tg * 32 + mi * 16 + g;
                const __nv_bfloat16* r0 = hs + tr * SPH + k16 + tig * 2;
                const __nv_bfloat16* r1 = hs + (tr + 8) * SPH + k16 + tig * 2;
                a[mi][0] = *(const u32*)r0;
                a[mi][1] = *(const u32*)r1;
                a[mi][2] = *(const u32*)(r0 + 8);
                a[mi][3] = *(const u32*)(r1 + 8);
            }
            u32 bb[8][2];
            #pragma unroll
            for (int ni = 0; ni < 8; ++ni) {
                const int ch = cg * 64 + ni * 8 + g;
                const __nv_bfloat16* wr = ws + ch * SPH + k16 + tig * 2;
                bb[ni][0] = *(const u32*)wr;
                bb[ni][1] = *(const u32*)(wr + 8);
            }
            #pragma unroll
            for (int mi = 0; mi < 2; ++mi)
                #pragma unroll
                for (int ni = 0; ni < 8; ++ni)
                    mma16816(acc[mi][ni], a[mi], bb[ni]);
        }

        // epilogue: D[t][ch]; (c0,c1)/(c2,c3) adjacent channel pairs -> u64 stores
        #pragma unroll
        for (int mi = 0; mi < 2; ++mi) {
            #pragma unroll
            for (int ni = 0; ni < 8; ++ni) {
                const int rp = ((ch0 + cg * 64 + ni * 8) >> 1) + tig;
                const u64 c0 = colb + mi * 16;
                g_z[(u64)rp * BT + c0]     = pk2u(__float_as_uint(acc[mi][ni][0]),
                                                  __float_as_uint(acc[mi][ni][1]));
                g_z[(u64)rp * BT + c0 + 8] = pk2u(__float_as_uint(acc[mi][ni][2]),
                                                  __float_as_uint(acc[mi][ni][3]));
            }
        }
    }
}

// ---------------- fused 40-layer WaveNet body ----------------
#define SM1_FLOATS (2 * RCD * (NT1 + 1) + 2 * WPL)
#define SM1_BYTES  (SM1_FLOATS * 4)

__global__ void __launch_bounds__(NT1, 1)
wn_main(const float* __restrict__ x, const float* __restrict__ start_w) {
    extern __shared__ float sm[];
    float* res0 = sm;
    float* res1 = res0 + RCD * (NT1 + 1);
    float* w0s  = res1 + RCD * (NT1 + 1);
    float* w1s  = w0s + WPL;

    const int tid = threadIdx.x;
    const int b = blockIdx.y;
    const int t = blockIdx.x * TILE1 - HALO + tid;
    const bool tin = (t >= 0) && (t < TD);
    const int col = b * TD + (tin ? t : 0);

    if (tid < RCD) {
        res0[tid * (NT1 + 1)] = 0.f;
        res1[tid * (NT1 + 1)] = 0.f;
    }

    const float xv = tin ? x[b * TD + t] : 0.f;
    #pragma unroll
    for (int c = 0; c < RCD; ++c)
        res0[c * (NT1 + 1) + tid + 1] = start_w[c] * xv;

    #pragma unroll 1
    for (int i = tid; i < WPL / 4; i += NT1)
        ((float4*)w0s)[i] = ((const float4*)g_wpack)[i];

    for (int l = 0; l < NLAY; ++l) {
        __syncthreads();   // the ONLY barrier per layer

        const int cur = l & 1;
        const float* rc = cur ? res1 : res0;
        float*       rn = cur ? res0 : res1;
        const float* wc = cur ? w1s  : w0s;
        float*       wp = cur ? w0s  : w1s;

        if (l + 1 < NLAY) {
            const float4* src = (const float4*)(g_wpack + (l + 1) * WPL);
            #pragma unroll 1
            for (int i = tid; i < WPL / 4; i += NT1) ((float4*)wp)[i] = src[i];
        }

        // ---- init accumulators from precomputed conditioning Z ----
        u64 f2[16], g2[16];
        if (tin) {
            const u64* zf = g_z + (u64)(l * 32) * BT + col;
            #pragma unroll
            for (int p = 0; p < 16; ++p) f2[p] = zf[(u64)p * BT];
            const u64* zg = g_z + (u64)(l * 32 + 16) * BT + col;
            #pragma unroll
            for (int p = 0; p < 16; ++p) g2[p] = zg[(u64)p * BT];
        } else {
            #pragma unroll
            for (int p = 0; p < 16; ++p) { f2[p] = 0ull; g2[p] = 0ull; }
        }

        // ---- conv (folded) filter part ----
        #pragma unroll 4
        for (int c = 0; c < RCD; ++c) {
            u64 vn2 = pk2(rc[c * (NT1 + 1) + tid]);
            u64 vc2 = pk2(rc[c * (NT1 + 1) + tid + 1]);
            const ulonglong2* a0 = (const ulonglong2*)(wc + OFF_FW0 + c * 32);
            const ulonglong2* a1 = (const ulonglong2*)(wc + OFF_FW1 + c * 32);
            #pragma unroll
            for (int q = 0; q < 8; ++q) {
                ulonglong2 w0 = a0[q], w1 = a1[q];
                fma2(f2[2 * q], w0.x, vn2); fma2(f2[2 * q + 1], w0.y, vn2);
                fma2(f2[2 * q], w1.x, vc2); fma2(f2[2 * q + 1], w1.y, vc2);
            }
        }
        float filt[32];
        #pragma unroll
        for (int p = 0; p < 16; ++p) {
            float2 v = upk(f2[p]);
            filt[2 * p]     = fast_tanh(v.x);
            filt[2 * p + 1] = fast_tanh(v.y);
        }

        // ---- conv (folded) gate part ----
        #pragma unroll 4
        for (int c = 0; c < RCD; ++c) {
            u64 vn2 = pk2(rc[c * (NT1 + 1) + tid]);
            u64 vc2 = pk2(rc[c * (NT1 + 1) + tid + 1]);
            const ulonglong2* a0 = (const ulonglong2*)(wc + OFF_GW0 + c * 32);
            const ulonglong2* a1 = (const ulonglong2*)(wc + OFF_GW1 + c * 32);
            #pragma unroll
            for (int q = 0; q < 8; ++q) {
                ulonglong2 w0 = a0[q], w1 = a1[q];
                fma2(g2[2 * q], w0.x, vn2); fma2(g2[2 * q + 1], w0.y, vn2);
                fma2(g2[2 * q], w1.x, vc2); fma2(g2[2 * q + 1], w1.y, vc2);
            }
        }
        #pragma unroll
        for (int p = 0; p < 16; ++p) {
            float2 v = upk(g2[p]);
            filt[2 * p]     *= fast_sig(v.x);
            filt[2 * p + 1] *= fast_sig(v.y);
        }

        // ---- out = OW @ fg ; residual -> next buffer ----
        u64 o2[16];
        #pragma unroll
        for (int p = 0; p < 16; ++p) o2[p] = 0ull;
        #pragma unroll
        for (int c = 0; c < DCD; ++c) {
            u64 v2 = pk2(filt[c]);
            const ulonglong2* a = (const ulonglong2*)(wc + OFF_OW + c * 32);
            #pragma unroll
            for (int q = 0; q < 8; ++q) {
                ulonglong2 w = a[q];
                fma2(o2[2 * q], w.x, v2); fma2(o2[2 * q + 1], w.y, v2);
            }
        }
        #pragma unroll
        for (int p = 0; p < 16; ++p) {
            float2 o = upk(o2[p]);
            rn[(2 * p) * (NT1 + 1) + tid + 1]     = rc[(2 * p) * (NT1 + 1) + tid + 1] + o.x;
            rn[(2 * p + 1) * (NT1 + 1) + tid + 1] = rc[(2 * p + 1) * (NT1 + 1) + tid + 1] + o.y;
        }
    }

    if (tid >= HALO && t < TD) {
        #pragma unroll
        for (int c = 0; c < RCD; ++c)
            g_skips[(b * RCD + c) * TD + t] =
                res0[c * (NT1 + 1) + tid + 1] - start_w[c] * xv;
    }
}

// ---------------- end stack: relu -> 256x32 -> relu -> 256x256 ----------------
#define SM2_FLOATS (SCD * TT2 + RCD * NCLS + RCD * TT2)
#define SM2_BYTES  (SM2_FLOATS * 4)

__global__ void __launch_bounds__(NT2, 1)
wn_end(float* __restrict__ out) {
    extern __shared__ float sm[];
    float* e_s = sm;                       // [256][TT2]
    float* w_s = e_s + SCD * TT2;          // [8192]
    float* s_s = w_s + RCD * NCLS;         // [32][TT2]

    const int tid = threadIdx.x;
    const int b = blockIdx.y;
    const int t0 = blockIdx.x * TT2;
    const int g = tid >> 7;
    const int tc = tid & 127;
    const int t = t0 + tc;

    #pragma unroll 1
    for (int i = tid; i < RCD * SCD; i += NT2) w_s[i] = g_e1[i];
    #pragma unroll 1
    for (int i = tid; i < RCD * TT2; i += NT2) {
        int c = i >> 7, tt = i & 127;
        s_s[i] = fmaxf(g_skips[(b * RCD + c) * TD + t0 + tt], 0.f);
    }
    __syncthreads();

    u64 acc[32];
    #pragma unroll
    for (int p = 0; p < 32; ++p) acc[p] = 0ull;
    #pragma unroll 2
    for (int c = 0; c < RCD; ++c) {
        u64 v2 = pk2(s_s[c * TT2 + tc]);
        const ulonglong2* wr = (const ulonglong2*)(w_s + c * SCD + (g << 6));
        #pragma unroll
        for (int q = 0; q < 16; ++q) {
            ulonglong2 a = wr[q];
            fma2(acc[2 * q], a.x, v2); fma2(acc[2 * q + 1], a.y, v2);
        }
    }
    #pragma unroll
    for (int p = 0; p < 32; ++p) {
        float2 v = upk(acc[p]);
        int sc = (g << 6) + 2 * p;
        e_s[sc * TT2 + tc]       = fmaxf(v.x, 0.f);
        e_s[(sc + 1) * TT2 + tc] = fmaxf(v.y, 0.f);
    }

    #pragma unroll
    for (int p = 0; p < 32; ++p) acc[p] = 0ull;
    for (int kk = 0; kk < SCD / RCD; ++kk) {
        __syncthreads();
        #pragma unroll 1
        for (int i = tid; i < RCD * NCLS; i += NT2) w_s[i] = g_e2[kk * RCD * NCLS + i];
        __syncthreads();
        #pragma unroll 2
        for (int c = 0; c < RCD; ++c) {
            u64 v2 = pk2(e_s[(kk * RCD + c) * TT2 + tc]);
            const ulonglong2* wr = (const ulonglong2*)(w_s + c * NCLS + (g << 6));
            #pragma unroll
            for (int q = 0; q < 16; ++q) {
                ulonglong2 a = wr[q];
                fma2(acc[2 * q], a.x, v2); fma2(acc[2 * q + 1], a.y, v2);
            }
        }
    }
    #pragma unroll
    for (int p = 0; p < 32; ++p) {
        float2 v = upk(acc[p]);
        int cls = (g << 6) + 2 * p;
        out[(b * NCLS + cls) * TD + t]       = v.x;
        out[(b * NCLS + cls + 1) * TD + t]   = v.y;
    }
}

// ---------------- launch ----------------
extern "C" void kernel_launch(void* const* d_in, const int* in_sizes, int n_in,
                              void* d_out, int out_size) {
    const float* x       = (const float*)d_in[0];
    const float* h       = (const float*)d_in[1];
    const float* start_w = (const float*)d_in[2];
    const float* dil_w   = (const float*)d_in[3];
    const float* f_w     = (const float*)d_in[4];
    const float* g_w     = (const float*)d_in[5];
    const float* cf_w    = (const float*)d_in[6];
    const float* cg_w    = (const float*)d_in[7];
    const float* out_w   = (const float*)d_in[8];
    const float* e1_w    = (const float*)d_in[9];
    const float* e2_w    = (const float*)d_in[10];
    float* out = (float*)d_out;

    cudaFuncSetAttribute(wn_cond, cudaFuncAttributeMaxDynamicSharedMemorySize, CSM2);
    cudaFuncSetAttribute(wn_main, cudaFuncAttributeMaxDynamicSharedMemorySize, SM1_BYTES);
    cudaFuncSetAttribute(wn_end,  cudaFuncAttributeMaxDynamicSharedMemorySize, SM2_BYTES);

    wn_pack<<<256, 256>>>(dil_w, f_w, g_w, cf_w, cg_w, out_w, e1_w, e2_w);
    wn_cond<<<512, 256, CSM2>>>(h);
    wn_main<<<dim3(NTILES, BD), NT1, SM1_BYTES>>>(x, start_w);
    wn_end<<<dim3(TD / TT2, BD), NT2, SM2_BYTES>>>(out);
}

// round 14
// speedup vs baseline: 1.6383x; 1.1670x over previous
#include <cuda_runtime.h>
#include <cuda_bf16.h>

// ---------------- dims ----------------
#define BD 4
#define TD 16384
#define BT (BD * TD)     // 65536 time-batch columns
#define RCD 32
#define DCD 32
#define SCD 256
#define NCLS 256
#define NCOND 80
#define NLAY 40

// main kernel tiling: 512 threads, single wave (140 blocks)
#define NT1 512
#define HALO 40
#define TILE1 472
#define NTILES 35

// packed per-layer weight layout (float offsets) -- conditioning on tensor path
#define OFF_FW0 0
#define OFF_FW1 1024
#define OFF_GW0 2048
#define OFF_GW1 3072
#define OFF_OW  4096
#define WPL     5120

// cond GEMM (mma.sync bf16): K = 240 (Whi|Whi|Wlo  x  hhi|hlo|hhi), 15 k-steps
#define CK 240
#define NKS 15
#define SPH 248          // bf16 row stride (words%32 = 28 -> conflict-free)
#define NCHT 20          // 2560 channels / 128 per tile

// end kernel tiling (HMMA e2)
#define ET 64            // time tile
#define EKS 768          // e2 split K: 256 whi|256 whi|256 wlo
#define EBS 776          // e smem bf16 row stride (388 words = 4 mod 32 -> conflict-free MMA loads)

// ---------------- device scratch (static, no allocation) ----------------
__device__ float g_wpack[NLAY * WPL];
__device__ __align__(16) __nv_bfloat16 g_wb[2560 * 256];   // cond weights bf16 split
__device__ float g_e1[RCD * SCD];
__device__ __align__(16) __nv_bfloat16 g_e2b[NCLS * EKS];  // e2 weights bf16 split
__device__ float g_skips[BD * RCD * TD];
__device__ unsigned long long g_z[1280ull * BT];           // cond pre-activations (f32 pairs)

// ---------------- helpers ----------------
typedef unsigned long long u64;
typedef unsigned int u32;

__device__ __forceinline__ u64 pk2(float v) {
    u64 r;
    asm("mov.b64 %0, {%1, %2};" : "=l"(r) : "f"(v), "f"(v));
    return r;
}
__device__ __forceinline__ u64 pk2u(u32 lo, u32 hi) {
    u64 r;
    asm("mov.b64 %0, {%1, %2};" : "=l"(r) : "r"(lo), "r"(hi));
    return r;
}
__device__ __forceinline__ void fma2(u64 &d, u64 a, u64 b) {
    asm("fma.rn.f32x2 %0, %1, %2, %0;" : "+l"(d) : "l"(a), "l"(b));
}
__device__ __forceinline__ float2 upk(u64 v) {
    float2 r;
    asm("mov.b64 {%0, %1}, %2;" : "=f"(r.x), "=f"(r.y) : "l"(v));
    return r;
}
__device__ __forceinline__ u32 smem_u32(const void* p) {
    u32 a;
    asm("{ .reg .u64 t; cvta.to.shared.u64 t, %1; cvt.u32.u64 %0, t; }" : "=r"(a) : "l"(p));
    return a;
}
__device__ __forceinline__ u32 bfpack(float a, float b) {
    u32 r;
    asm("cvt.rn.bf16x2.f32 %0, %1, %2;" : "=r"(r) : "f"(b), "f"(a));
    return r;
}

__device__ __forceinline__ float fast_tanh(float x) {
    float a = fminf(fmaxf(-2.f * x, -60.f), 60.f);
    float e = __expf(a);
    return (1.f - e) * __fdividef(1.f, 1.f + e);
}
__device__ __forceinline__ float fast_sig(float x) {
    float a = fminf(fmaxf(-x, -60.f), 60.f);
    float e = __expf(a);
    return __fdividef(1.f, 1.f + e);
}

// warp-level bf16 MMA: D(16x8,f32) += A(16x16,row) * B(16x8,col)
__device__ __forceinline__ void mma16816(float* c, const u32* a, const u32* b) {
    asm volatile(
        "mma.sync.aligned.m16n8k16.row.col.f32.bf16.bf16.f32 "
        "{%0,%1,%2,%3}, {%4,%5,%6,%7}, {%8,%9}, {%0,%1,%2,%3};"
        : "+f"(c[0]), "+f"(c[1]), "+f"(c[2]), "+f"(c[3])
        : "r"(a[0]), "r"(a[1]), "r"(a[2]), "r"(a[3]), "r"(b[0]), "r"(b[1]));
}

// ---------------- weight repack + compose kernel ----------------
__global__ void wn_pack(const float* __restrict__ dil_w, const float* __restrict__ f_w,
                        const float* __restrict__ g_w,   const float* __restrict__ cf_w,
                        const float* __restrict__ cg_w,  const float* __restrict__ out_w,
                        const float* __restrict__ e1_w,  const float* __restrict__ e2_w) {
    int stride = gridDim.x * blockDim.x;
    int tid0 = blockIdx.x * blockDim.x + threadIdx.x;

    for (int i = tid0; i < NLAY * WPL; i += stride) {
        int l = i / WPL, off = i % WPL;
        float v;
        if (off < 4096) {
            int which = off >> 10;
            int o = off & 1023;
            int c = o >> 5, ch = o & 31;
            int k = which & 1;
            const float* base = (which < 2) ? f_w : g_w;
            float s = 0.f;
            #pragma unroll 8
            for (int d = 0; d < 32; ++d)
                s += base[(l * 32 + ch) * 32 + d] * dil_w[((l * 32 + d) * 32 + c) * 2 + k];
            v = s;
        } else {                                      // OW packed [d][r]
            int o = off - 4096; int c = o >> 5, r = o & 31;
            v = out_w[(l * 32 + r) * 32 + c];
        }
        g_wpack[i] = v;
    }
    // cond weights bf16-split K-concat: row r = l*64 + (ch<32 ? CF ch : CG ch-32)
    for (int j = tid0; j < 2560 * 256; j += stride) {
        int r = j >> 8, k = j & 255;
        int l = r >> 6, ch = r & 63;
        const float* src = (ch < 32) ? cf_w + (l * 32 + ch) * NCOND
                                     : cg_w + (l * 32 + (ch - 32)) * NCOND;
        __nv_bfloat16 o;
        if (k < 80) {
            o = __float2bfloat16(src[k]);                                 // Whi (x hhi)
        } else if (k < 160) {
            o = __float2bfloat16(src[k - 80]);                            // Whi (x hlo)
        } else if (k < 240) {
            float w = src[k - 160];
            __nv_bfloat16 hi = __float2bfloat16(w);
            o = __float2bfloat16(w - __bfloat162float(hi));               // Wlo (x hhi)
        } else {
            o = __float2bfloat16(0.f);
        }
        g_wb[j] = o;
    }
    for (int j = tid0; j < RCD * SCD; j += stride) {
        int c = j >> 8, s = j & 255;
        g_e1[j] = e1_w[s * RCD + c];
    }
    // e2 weights bf16-split K-concat: k<256 whi(x ehi) | 256..511 whi(x elo) | 512.. wlo(x ehi)
    for (int j = tid0; j < NCLS * EKS; j += stride) {
        int o = j / EKS, k = j % EKS;
        float w = e2_w[o * SCD + (k & 255)];
        __nv_bfloat16 hi = __float2bfloat16(w);
        g_e2b[j] = (k < 512) ? hi : __float2bfloat16(w - __bfloat162float(hi));
    }
}

// ---------------- cond GEMM: Z = Wc @ h, bf16-split mma.sync ----------------
#define HS_OFF  0
#define WSA_OFF (128 * SPH * 2)                 // 63488
#define WSB_OFF (WSA_OFF + 128 * SPH * 2)       // 126976
#define FB_OFF  WSA_OFF                         // fbuf (41280 B) reuses wsA pre-loop
#define CSM2    (WSB_OFF + 128 * SPH * 2)       // 190464 B

__global__ void __launch_bounds__(256, 1)
wn_cond(const float* __restrict__ h) {
    extern __shared__ char csm[];
    __nv_bfloat16* hs = (__nv_bfloat16*)(csm + HS_OFF);
    float* fbuf = (float*)(csm + FB_OFF);

    const int tid = threadIdx.x;
    const int b = blockIdx.x >> 7;
    const int t0 = (blockIdx.x & 127) << 7;

    // phase 1: coalesced h tile -> fbuf[c][t]
    #pragma unroll 1
    for (int idx = tid; idx < NCOND * 128; idx += 256) {
        int c = idx >> 7, t = idx & 127;
        fbuf[c * 129 + t] = h[(b * NCOND + c) * TD + t0 + t];
    }
    __syncthreads();
    // phase 2: transpose-convert fbuf -> hs[t][k]
    #pragma unroll 1
    for (int idx = tid; idx < NCOND * 128; idx += 256) {
        int t = idx / NCOND, c = idx % NCOND;
        float hv = fbuf[c * 129 + t];
        __nv_bfloat16 hi = __float2bfloat16(hv);
        __nv_bfloat16 lo = __float2bfloat16(hv - __bfloat162float(hi));
        __nv_bfloat16* row = hs + t * SPH;
        row[c] = hi;
        row[c + 80] = lo;
        row[c + 160] = hi;
    }
    __syncthreads();

    const u32 ws_s[2] = { smem_u32(csm + WSA_OFF), smem_u32(csm + WSB_OFF) };

    // prefill ws buffer 0 with channel-tile 0
    {
        const char* srcb = (const char*)g_wb;
        #pragma unroll 1
        for (int i2 = 0; i2 < 15; ++i2) {
            int idx = tid + i2 * 256;
            int r = idx / 30, ck = idx % 30;
            u32 d = ws_s[0] + r * (SPH * 2) + ck * 16;
            asm volatile("cp.async.ca.shared.global [%0], [%1], 16;"
                         :: "r"(d), "l"(srcb + (r * 256 + ck * 8) * 2) : "memory");
        }
        asm volatile("cp.async.commit_group;" ::: "memory");
    }

    const int wid = tid >> 5, lane = tid & 31;
    const int tg = wid >> 1, cg = wid & 1;
    const int g = lane >> 2, tig = lane & 3;
    const u64 colb = (u64)blockIdx.x * 128 + tg * 32 + g;

    #pragma unroll 1
    for (int nc = 0; nc < NCHT; ++nc) {
        const int cur = nc & 1;
        __syncthreads();

        if (nc + 1 < NCHT) {
            const char* srcb = (const char*)(g_wb + (u64)(nc + 1) * 128 * 256);
            #pragma unroll 1
            for (int i2 = 0; i2 < 15; ++i2) {
                int idx = tid + i2 * 256;
                int r = idx / 30, ck = idx % 30;
                u32 d = ws_s[cur ^ 1] + r * (SPH * 2) + ck * 16;
                asm volatile("cp.async.ca.shared.global [%0], [%1], 16;"
                             :: "r"(d), "l"(srcb + (r * 256 + ck * 8) * 2) : "memory");
            }
            asm volatile("cp.async.commit_group;" ::: "memory");
            asm volatile("cp.async.wait_group 1;" ::: "memory");
        } else {
            asm volatile("cp.async.wait_group 0;" ::: "memory");
        }
        __syncthreads();

        const __nv_bfloat16* ws = (const __nv_bfloat16*)(csm + (cur ? WSB_OFF : WSA_OFF));
        const int ch0 = nc * 128;

        float acc[2][8][4];
        #pragma unroll
        for (int mi = 0; mi < 2; ++mi)
            #pragma unroll
            for (int ni = 0; ni < 8; ++ni)
                #pragma unroll
                for (int j = 0; j < 4; ++j) acc[mi][ni][j] = 0.f;

        #pragma unroll 1
        for (int kc = 0; kc < NKS; ++kc) {
            const int k16 = kc * 16;
            u32 a[2][4];
            #pragma unroll
            for (int mi = 0; mi < 2; ++mi) {
                const int tr = tg * 32 + mi * 16 + g;
                const __nv_bfloat16* r0 = hs + tr * SPH + k16 + tig * 2;
                const __nv_bfloat16* r1 = hs + (tr + 8) * SPH + k16 + tig * 2;
                a[mi][0] = *(const u32*)r0;
                a[mi][1] = *(const u32*)r1;
                a[mi][2] = *(const u32*)(r0 + 8);
                a[mi][3] = *(const u32*)(r1 + 8);
            }
            u32 bb[8][2];
            #pragma unroll
            for (int ni = 0; ni < 8; ++ni) {
                const int ch = cg * 64 + ni * 8 + g;
                const __nv_bfloat16* wr = ws + ch * SPH + k16 + tig * 2;
                bb[ni][0] = *(const u32*)wr;
                bb[ni][1] = *(const u32*)(wr + 8);
            }
            #pragma unroll
            for (int mi = 0; mi < 2; ++mi)
                #pragma unroll
                for (int ni = 0; ni < 8; ++ni)
                    mma16816(acc[mi][ni], a[mi], bb[ni]);
        }

        #pragma unroll
        for (int mi = 0; mi < 2; ++mi) {
            #pragma unroll
            for (int ni = 0; ni < 8; ++ni) {
                const int rp = ((ch0 + cg * 64 + ni * 8) >> 1) + tig;
                const u64 c0 = colb + mi * 16;
                g_z[(u64)rp * BT + c0]     = pk2u(__float_as_uint(acc[mi][ni][0]),
                                                  __float_as_uint(acc[mi][ni][1]));
                g_z[(u64)rp * BT + c0 + 8] = pk2u(__float_as_uint(acc[mi][ni][2]),
                                                  __float_as_uint(acc[mi][ni][3]));
            }
        }
    }
}

// ---------------- fused 40-layer WaveNet body ----------------
#define SM1_FLOATS (2 * RCD * (NT1 + 1) + 2 * WPL)
#define SM1_BYTES  (SM1_FLOATS * 4)

__global__ void __launch_bounds__(NT1, 1)
wn_main(const float* __restrict__ x, const float* __restrict__ start_w) {
    extern __shared__ float sm[];
    float* res0 = sm;
    float* res1 = res0 + RCD * (NT1 + 1);
    float* w0s  = res1 + RCD * (NT1 + 1);
    float* w1s  = w0s + WPL;

    const int tid = threadIdx.x;
    const int b = blockIdx.y;
    const int t = blockIdx.x * TILE1 - HALO + tid;
    const bool tin = (t >= 0) && (t < TD);
    const int col = b * TD + (tin ? t : 0);

    if (tid < RCD) {
        res0[tid * (NT1 + 1)] = 0.f;
        res1[tid * (NT1 + 1)] = 0.f;
    }

    const float xv = tin ? x[b * TD + t] : 0.f;
    #pragma unroll
    for (int c = 0; c < RCD; ++c)
        res0[c * (NT1 + 1) + tid + 1] = start_w[c] * xv;

    #pragma unroll 1
    for (int i = tid; i < WPL / 4; i += NT1)
        ((float4*)w0s)[i] = ((const float4*)g_wpack)[i];

    for (int l = 0; l < NLAY; ++l) {
        __syncthreads();   // the ONLY barrier per layer

        const int cur = l & 1;
        const float* rc = cur ? res1 : res0;
        float*       rn = cur ? res0 : res1;
        const float* wc = cur ? w1s  : w0s;
        float*       wp = cur ? w0s  : w1s;

        if (l + 1 < NLAY) {
            const float4* src = (const float4*)(g_wpack + (l + 1) * WPL);
            #pragma unroll 1
            for (int i = tid; i < WPL / 4; i += NT1) ((float4*)wp)[i] = src[i];
        }

        // ---- init accumulators from precomputed conditioning Z ----
        u64 f2[16], g2[16];
        if (tin) {
            const u64* zf = g_z + (u64)(l * 32) * BT + col;
            #pragma unroll
            for (int p = 0; p < 16; ++p) f2[p] = zf[(u64)p * BT];
            const u64* zg = g_z + (u64)(l * 32 + 16) * BT + col;
            #pragma unroll
            for (int p = 0; p < 16; ++p) g2[p] = zg[(u64)p * BT];
        } else {
            #pragma unroll
            for (int p = 0; p < 16; ++p) { f2[p] = 0ull; g2[p] = 0ull; }
        }

        // ---- conv (folded) filter part ----
        #pragma unroll 4
        for (int c = 0; c < RCD; ++c) {
            u64 vn2 = pk2(rc[c * (NT1 + 1) + tid]);
            u64 vc2 = pk2(rc[c * (NT1 + 1) + tid + 1]);
            const ulonglong2* a0 = (const ulonglong2*)(wc + OFF_FW0 + c * 32);
            const ulonglong2* a1 = (const ulonglong2*)(wc + OFF_FW1 + c * 32);
            #pragma unroll
            for (int q = 0; q < 8; ++q) {
                ulonglong2 w0 = a0[q], w1 = a1[q];
                fma2(f2[2 * q], w0.x, vn2); fma2(f2[2 * q + 1], w0.y, vn2);
                fma2(f2[2 * q], w1.x, vc2); fma2(f2[2 * q + 1], w1.y, vc2);
            }
        }
        float filt[32];
        #pragma unroll
        for (int p = 0; p < 16; ++p) {
            float2 v = upk(f2[p]);
            filt[2 * p]     = fast_tanh(v.x);
            filt[2 * p + 1] = fast_tanh(v.y);
        }

        // ---- conv (folded) gate part ----
        #pragma unroll 4
        for (int c = 0; c < RCD; ++c) {
            u64 vn2 = pk2(rc[c * (NT1 + 1) + tid]);
            u64 vc2 = pk2(rc[c * (NT1 + 1) + tid + 1]);
            const ulonglong2* a0 = (const ulonglong2*)(wc + OFF_GW0 + c * 32);
            const ulonglong2* a1 = (const ulonglong2*)(wc + OFF_GW1 + c * 32);
            #pragma unroll
            for (int q = 0; q < 8; ++q) {
                ulonglong2 w0 = a0[q], w1 = a1[q];
                fma2(g2[2 * q], w0.x, vn2); fma2(g2[2 * q + 1], w0.y, vn2);
                fma2(g2[2 * q], w1.x, vc2); fma2(g2[2 * q + 1], w1.y, vc2);
            }
        }
        #pragma unroll
        for (int p = 0; p < 16; ++p) {
            float2 v = upk(g2[p]);
            filt[2 * p]     *= fast_sig(v.x);
            filt[2 * p + 1] *= fast_sig(v.y);
        }

        // ---- out = OW @ fg ; residual -> next buffer ----
        u64 o2[16];
        #pragma unroll
        for (int p = 0; p < 16; ++p) o2[p] = 0ull;
        #pragma unroll
        for (int c = 0; c < DCD; ++c) {
            u64 v2 = pk2(filt[c]);
            const ulonglong2* a = (const ulonglong2*)(wc + OFF_OW + c * 32);
            #pragma unroll
            for (int q = 0; q < 8; ++q) {
                ulonglong2 w = a[q];
                fma2(o2[2 * q], w.x, v2); fma2(o2[2 * q + 1], w.y, v2);
            }
        }
        #pragma unroll
        for (int p = 0; p < 16; ++p) {
            float2 o = upk(o2[p]);
            rn[(2 * p) * (NT1 + 1) + tid + 1]     = rc[(2 * p) * (NT1 + 1) + tid + 1] + o.x;
            rn[(2 * p + 1) * (NT1 + 1) + tid + 1] = rc[(2 * p + 1) * (NT1 + 1) + tid + 1] + o.y;
        }
    }

    if (tid >= HALO && t < TD) {
        #pragma unroll
        for (int c = 0; c < RCD; ++c)
            g_skips[(b * RCD + c) * TD + t] =
                res0[c * (NT1 + 1) + tid + 1] - start_w[c] * xv;
    }
}

// ---------------- end stack: relu -> 256x32 (fp32) -> relu -> 256x256 (HMMA) ----------------
// smem bytes: s_s 8192 | w1_s 32768 | eb 64*776*2=99328 (reused as D_s 256*65*4=66560) |
//             w2 256*136*2=69632   -> total 209920
#define E_S_OFF  0
#define E_W1_OFF 8192
#define E_EB_OFF 40960
#define E_W2_OFF 140288
#define CSM3     209920

__global__ void __launch_bounds__(512, 1)
wn_end(float* __restrict__ out) {
    extern __shared__ char esm[];
    float* s_s  = (float*)(esm + E_S_OFF);              // [32][64]
    float* w1_s = (float*)(esm + E_W1_OFF);             // [32][256]
    __nv_bfloat16* eb = (__nv_bfloat16*)(esm + E_EB_OFF); // [64][EBS]
    __nv_bfloat16* w2 = (__nv_bfloat16*)(esm + E_W2_OFF); // [256][136] chunk
    float* D_s  = (float*)(esm + E_EB_OFF);             // [256][65] reuse

    const int tid = threadIdx.x;
    const int b = blockIdx.y;
    const int t0 = blockIdx.x * ET;

    #pragma unroll 1
    for (int i = tid; i < RCD * ET; i += 512) {
        int c = i >> 6, t = i & 63;
        s_s[i] = fmaxf(g_skips[(b * RCD + c) * TD + t0 + t], 0.f);
    }
    #pragma unroll 1
    for (int i = tid; i < RCD * SCD; i += 512) w1_s[i] = g_e1[i];
    __syncthreads();

    // ---- e1 fp32: e[t][ch], thread = (tc = tid&63, ocg = tid>>6 -> 32 ch) ----
    {
        const int tc = tid & 63, ocg = tid >> 6;
        u64 acc1[16];
        #pragma unroll
        for (int p = 0; p < 16; ++p) acc1[p] = 0ull;
        #pragma unroll 4
        for (int c = 0; c < RCD; ++c) {
            u64 v2 = pk2(s_s[c * 64 + tc]);
            const ulonglong2* wr = (const ulonglong2*)(w1_s + c * SCD + ocg * 32);
            #pragma unroll
            for (int q = 0; q < 8; ++q) {
                ulonglong2 a = wr[q];
                fma2(acc1[2 * q], a.x, v2); fma2(acc1[2 * q + 1], a.y, v2);
            }
        }
        // relu + bf16 split -> eb[t][k]: [c]=ehi, [256+c]=elo, [512+c]=ehi
        __nv_bfloat16* row = eb + tc * EBS;
        #pragma unroll
        for (int p = 0; p < 16; ++p) {
            float2 v = upk(acc1[p]);
            float e0 = fmaxf(v.x, 0.f), e1v = fmaxf(v.y, 0.f);
            float h0 = __bfloat162float(__float2bfloat16(e0));
            float h1 = __bfloat162float(__float2bfloat16(e1v));
            u32 hip = bfpack(e0, e1v);
            u32 lop = bfpack(e0 - h0, e1v - h1);
            int ch = ocg * 32 + 2 * p;
            *(u32*)(row + ch)       = hip;
            *(u32*)(row + 256 + ch) = lop;
            *(u32*)(row + 512 + ch) = hip;
        }
    }

    // ---- e2 HMMA: logits[t][ch] over K=768, 6 chunks of 128 ----
    const int wid = tid >> 5, lane = tid & 31;
    const int tg = wid >> 2, cg = wid & 3;     // 4 time-groups x 4 ch-groups
    const int g = lane >> 2, tig = lane & 3;

    float acc[8][4];
    #pragma unroll
    for (int ni = 0; ni < 8; ++ni)
        #pragma unroll
        for (int j = 0; j < 4; ++j) acc[ni][j] = 0.f;

    const u32 w2u = smem_u32(w2);
    #pragma unroll 1
    for (int kc = 0; kc < 6; ++kc) {
        __syncthreads();   // phase A done (kc=0) / prior chunk reads done
        #pragma unroll
        for (int j = 0; j < 8; ++j) {
            int idx = tid + j * 512;
            int r = idx >> 4, sg = idx & 15;
            u32 d = w2u + r * 272 + sg * 16;
            const char* s = (const char*)g_e2b + (r * EKS + kc * 128 + sg * 8) * 2;
            asm volatile("cp.async.ca.shared.global [%0], [%1], 16;"
                         :: "r"(d), "l"(s) : "memory");
        }
        asm volatile("cp.async.commit_group;" ::: "memory");
        asm volatile("cp.async.wait_group 0;" ::: "memory");
        __syncthreads();

        #pragma unroll
        for (int ks = 0; ks < 8; ++ks) {
            const int kg = kc * 128 + ks * 16;     // eb column
            const __nv_bfloat16* r0 = eb + (tg * 16 + g) * EBS + kg + tig * 2;
            const __nv_bfloat16* r1 = r0 + 8 * EBS;
            u32 a[4];
            a[0] = *(const u32*)r0;
            a[1] = *(const u32*)r1;
            a[2] = *(const u32*)(r0 + 8);
            a[3] = *(const u32*)(r1 + 8);
            #pragma unroll
            for (int ni = 0; ni < 8; ++ni) {
                const int ch = cg * 64 + ni * 8 + g;
                const __nv_bfloat16* wr = w2 + ch * 136 + ks * 16 + tig * 2;
                u32 bb[2];
                bb[0] = *(const u32*)wr;
                bb[1] = *(const u32*)(wr + 8);
                mma16816(acc[ni], a, bb);
            }
        }
    }

    __syncthreads();   // all eb reads done before reuse as D_s
    #pragma unroll
    for (int ni = 0; ni < 8; ++ni) {
        const int ch = cg * 64 + ni * 8 + tig * 2;
        const int tt = tg * 16 + g;
        D_s[ch * 65 + tt]           = acc[ni][0];
        D_s[(ch + 1) * 65 + tt]     = acc[ni][1];
        D_s[ch * 65 + tt + 8]       = acc[ni][2];
        D_s[(ch + 1) * 65 + tt + 8] = acc[ni][3];
    }
    __syncthreads();

    #pragma unroll 1
    for (int i = tid; i < NCLS * ET; i += 512) {
        int ch = i >> 6, t = i & 63;
        out[(b * NCLS + ch) * TD + t0 + t] = D_s[ch * 65 + t];
    }
}

// ---------------- launch ----------------
extern "C" void kernel_launch(void* const* d_in, const int* in_sizes, int n_in,
                              void* d_out, int out_size) {
    const float* x       = (const float*)d_in[0];
    const float* h       = (const float*)d_in[1];
    const float* start_w = (const float*)d_in[2];
    const float* dil_w   = (const float*)d_in[3];
    const float* f_w     = (const float*)d_in[4];
    const float* g_w     = (const float*)d_in[5];
    const float* cf_w    = (const float*)d_in[6];
    const float* cg_w    = (const float*)d_in[7];
    const float* out_w   = (const float*)d_in[8];
    const float* e1_w    = (const float*)d_in[9];
    const float* e2_w    = (const float*)d_in[10];
    float* out = (float*)d_out;

    cudaFuncSetAttribute(wn_cond, cudaFuncAttributeMaxDynamicSharedMemorySize, CSM2);
    cudaFuncSetAttribute(wn_main, cudaFuncAttributeMaxDynamicSharedMemorySize, SM1_BYTES);
    cudaFuncSetAttribute(wn_end,  cudaFuncAttributeMaxDynamicSharedMemorySize, CSM3);

    wn_pack<<<256, 256>>>(dil_w, f_w, g_w, cf_w, cg_w, out_w, e1_w, e2_w);
    wn_cond<<<512, 256, CSM2>>>(h);
    wn_main<<<dim3(NTILES, BD), NT1, SM1_BYTES>>>(x, start_w);
    wn_end<<<dim3(TD / ET, BD), 512, CSM3>>>(out);
}

// round 16
// speedup vs baseline: 2.4001x; 1.4650x over previous
#include <cuda_runtime.h>
#include <cuda_bf16.h>

// ---------------- dims ----------------
#define BD 4
#define TD 16384
#define BT (BD * TD)     // 65536 time-batch columns
#define RCD 32
#define SCD 256
#define NCLS 256
#define NCOND 80
#define NLAY 40

// main kernel tiling: 512 threads = 16 warps x 32 time rows, single wave (140 blocks)
#define NT1 512
#define HALO 40
#define TILE1 472
#define NTILES 35

// cond GEMM (mma.sync bf16): K = 240 (Whi|Whi|Wlo  x  hhi|hlo|hhi), 15 k-steps
#define NKS 15
#define SPH 248          // bf16 row stride (words%32 = 28 -> conflict-free)
#define NCHT 20          // 2560 channels / 128 per tile

// end kernel tiling (HMMA e2)
#define ET 64
#define EKS 768
#define EBS 776

// main HMMA layer-weight pack (u32 words)
#define WB1_W 4352       // conv B tile: 64 ch x 136 bf16 (128 k + 8 pad) = 4352 u32
#define OWB_W 1152       // OW  B tile: 32 n  x 72 bf16  (64 k + 8 pad)  = 1152 u32
#define WLW   (WB1_W + OWB_W)   // 5504 u32 per layer
#define RSW   40         // fp32 residual row stride (8g+2tig -> conflict-free LDS.64)

// ---------------- device scratch (static, no allocation) ----------------
__device__ __align__(16) unsigned int g_wlay[NLAY * WLW];   // main layer weights bf16-split
__device__ __align__(16) __nv_bfloat16 g_wb[2560 * 256];    // cond weights bf16 split
__device__ float g_e1[RCD * SCD];
__device__ __align__(16) __nv_bfloat16 g_e2b[NCLS * EKS];   // e2 weights bf16 split
__device__ float g_skips[BD * RCD * TD];
__device__ unsigned long long g_z[1280ull * BT];            // cond pre-activations (f32 pairs)

// ---------------- helpers ----------------
typedef unsigned long long u64;
typedef unsigned int u32;

__device__ __forceinline__ u64 pk2(float v) {
    u64 r;
    asm("mov.b64 %0, {%1, %2};" : "=l"(r) : "f"(v), "f"(v));
    return r;
}
__device__ __forceinline__ u64 pk2u(u32 lo, u32 hi) {
    u64 r;
    asm("mov.b64 %0, {%1, %2};" : "=l"(r) : "r"(lo), "r"(hi));
    return r;
}
__device__ __forceinline__ void fma2(u64 &d, u64 a, u64 b) {
    asm("fma.rn.f32x2 %0, %1, %2, %0;" : "+l"(d) : "l"(a), "l"(b));
}
__device__ __forceinline__ float2 upk(u64 v) {
    float2 r;
    asm("mov.b64 {%0, %1}, %2;" : "=f"(r.x), "=f"(r.y) : "l"(v));
    return r;
}
__device__ __forceinline__ u32 smem_u32(const void* p) {
    u32 a;
    asm("{ .reg .u64 t; cvta.to.shared.u64 t, %1; cvt.u32.u64 %0, t; }" : "=r"(a) : "l"(p));
    return a;
}
__device__ __forceinline__ u32 bfpack(float a, float b) {
    u32 r;
    asm("cvt.rn.bf16x2.f32 %0, %1, %2;" : "=r"(r) : "f"(b), "f"(a));
    return r;
}

__device__ __forceinline__ float fast_tanh(float x) {
    float a = fminf(fmaxf(-2.f * x, -60.f), 60.f);
    float e = __expf(a);
    return (1.f - e) * __fdividef(1.f, 1.f + e);
}
__device__ __forceinline__ float fast_sig(float x) {
    float a = fminf(fmaxf(-x, -60.f), 60.f);
    float e = __expf(a);
    return __fdividef(1.f, 1.f + e);
}

// warp-level bf16 MMA: D(16x8,f32) += A(16x16,row) * B(16x8,col)
__device__ __forceinline__ void mma16816(float* c, const u32* a, const u32* b) {
    asm volatile(
        "mma.sync.aligned.m16n8k16.row.col.f32.bf16.bf16.f32 "
        "{%0,%1,%2,%3}, {%4,%5,%6,%7}, {%8,%9}, {%0,%1,%2,%3};"
        : "+f"(c[0]), "+f"(c[1]), "+f"(c[2]), "+f"(c[3])
        : "r"(a[0]), "r"(a[1]), "r"(a[2]), "r"(a[3]), "r"(b[0]), "r"(b[1]));
}

// ---------------- pack helpers ----------------
// conv B value at [l][ch(0-31 filt,32-63 gate)][kk 0..135]
// k layout: 0-31 FW1(cur) hi | 32-63 FW0(prev) hi | 64-95 FW1 lo | 96-127 FW0 lo | pad
__device__ float wl1val(const float* f_w, const float* g_w, const float* dil_w,
                        int l, int ch, int kk) {
    if (kk >= 128) return 0.f;
    int sub = kk >> 5, c = kk & 31;
    int dk = (sub & 1) ? 0 : 1;   // sub 0,2 -> dil k=1 (cur); sub 1,3 -> k=0 (prev)
    const float* base = (ch < 32) ? f_w + (l * 32 + ch) * 32
                                  : g_w + (l * 32 + (ch - 32)) * 32;
    float s = 0.f;
    #pragma unroll 8
    for (int d = 0; d < 32; ++d)
        s += base[d] * dil_w[((l * 32 + d) * 32 + c) * 2 + dk];
    if (sub < 2) return s;
    return s - __bfloat162float(__float2bfloat16(s));
}
// OW B value at [l][n][kk 0..71]: 0-31 hi | 32-63 lo | pad
__device__ float owval(const float* out_w, int l, int n, int kk) {
    if (kk >= 64) return 0.f;
    float v = out_w[(l * 32 + n) * 32 + (kk & 31)];
    if (kk < 32) return v;
    return v - __bfloat162float(__float2bfloat16(v));
}

// ---------------- weight repack + compose kernel ----------------
__global__ void wn_pack(const float* __restrict__ dil_w, const float* __restrict__ f_w,
                        const float* __restrict__ g_w,   const float* __restrict__ cf_w,
                        const float* __restrict__ cg_w,  const float* __restrict__ out_w,
                        const float* __restrict__ e1_w,  const float* __restrict__ e2_w) {
    int stride = gridDim.x * blockDim.x;
    int tid0 = blockIdx.x * blockDim.x + threadIdx.x;

    // main layer weights (bf16-split, u32 pairs)
    for (int i = tid0; i < NLAY * WLW; i += stride) {
        int l = i / WLW, p = i % WLW;
        float v0, v1;
        if (p < WB1_W) {
            int ch = p / 68, wi = p % 68;
            v0 = wl1val(f_w, g_w, dil_w, l, ch, wi * 2);
            v1 = wl1val(f_w, g_w, dil_w, l, ch, wi * 2 + 1);
        } else {
            int q = p - WB1_W;
            int n = q / 36, wi = q % 36;
            v0 = owval(out_w, l, n, wi * 2);
            v1 = owval(out_w, l, n, wi * 2 + 1);
        }
        g_wlay[i] = bfpack(v0, v1);
    }
    // cond weights bf16-split K-concat
    for (int j = tid0; j < 2560 * 256; j += stride) {
        int r = j >> 8, k = j & 255;
        int l = r >> 6, ch = r & 63;
        const float* src = (ch < 32) ? cf_w + (l * 32 + ch) * NCOND
                                     : cg_w + (l * 32 + (ch - 32)) * NCOND;
        __nv_bfloat16 o;
        if (k < 80) {
            o = __float2bfloat16(src[k]);
        } else if (k < 160) {
            o = __float2bfloat16(src[k - 80]);
        } else if (k < 240) {
            float w = src[k - 160];
            __nv_bfloat16 hi = __float2bfloat16(w);
            o = __float2bfloat16(w - __bfloat162float(hi));
        } else {
            o = __float2bfloat16(0.f);
        }
        g_wb[j] = o;
    }
    for (int j = tid0; j < RCD * SCD; j += stride) {
        int c = j >> 8, s = j & 255;
        g_e1[j] = e1_w[s * RCD + c];
    }
    for (int j = tid0; j < NCLS * EKS; j += stride) {
        int o = j / EKS, k = j % EKS;
        float w = e2_w[o * SCD + (k & 255)];
        __nv_bfloat16 hi = __float2bfloat16(w);
        g_e2b[j] = (k < 512) ? hi : __float2bfloat16(w - __bfloat162float(hi));
    }
}

// ---------------- cond GEMM: Z = Wc @ h, bf16-split mma.sync (unchanged) ----------------
#define HS_OFF  0
#define WSA_OFF (128 * SPH * 2)
#define WSB_OFF (WSA_OFF + 128 * SPH * 2)
#define FB_OFF  WSA_OFF
#define CSM2    (WSB_OFF + 128 * SPH * 2)

__global__ void __launch_bounds__(256, 1)
wn_cond(const float* __restrict__ h) {
    extern __shared__ char csm[];
    __nv_bfloat16* hs = (__nv_bfloat16*)(csm + HS_OFF);
    float* fbuf = (float*)(csm + FB_OFF);

    const int tid = threadIdx.x;
    const int b = blockIdx.x >> 7;
    const int t0 = (blockIdx.x & 127) << 7;

    #pragma unroll 1
    for (int idx = tid; idx < NCOND * 128; idx += 256) {
        int c = idx >> 7, t = idx & 127;
        fbuf[c * 129 + t] = h[(b * NCOND + c) * TD + t0 + t];
    }
    __syncthreads();
    #pragma unroll 1
    for (int idx = tid; idx < NCOND * 128; idx += 256) {
        int t = idx / NCOND, c = idx % NCOND;
        float hv = fbuf[c * 129 + t];
        __nv_bfloat16 hi = __float2bfloat16(hv);
        __nv_bfloat16 lo = __float2bfloat16(hv - __bfloat162float(hi));
        __nv_bfloat16* row = hs + t * SPH;
        row[c] = hi;
        row[c + 80] = lo;
        row[c + 160] = hi;
    }
    __syncthreads();

    const u32 ws_s[2] = { smem_u32(csm + WSA_OFF), smem_u32(csm + WSB_OFF) };

    {
        const char* srcb = (const char*)g_wb;
        #pragma unroll 1
        for (int i2 = 0; i2 < 15; ++i2) {
            int idx = tid + i2 * 256;
            int r = idx / 30, ck = idx % 30;
            u32 d = ws_s[0] + r * (SPH * 2) + ck * 16;
            asm volatile("cp.async.ca.shared.global [%0], [%1], 16;"
                         :: "r"(d), "l"(srcb + (r * 256 + ck * 8) * 2) : "memory");
        }
        asm volatile("cp.async.commit_group;" ::: "memory");
    }

    const int wid = tid >> 5, lane = tid & 31;
    const int tg = wid >> 1, cg = wid & 1;
    const int g = lane >> 2, tig = lane & 3;
    const u64 colb = (u64)blockIdx.x * 128 + tg * 32 + g;

    #pragma unroll 1
    for (int nc = 0; nc < NCHT; ++nc) {
        const int cur = nc & 1;
        __syncthreads();

        if (nc + 1 < NCHT) {
            const char* srcb = (const char*)(g_wb + (u64)(nc + 1) * 128 * 256);
            #pragma unroll 1
            for (int i2 = 0; i2 < 15; ++i2) {
                int idx = tid + i2 * 256;
                int r = idx / 30, ck = idx % 30;
                u32 d = ws_s[cur ^ 1] + r * (SPH * 2) + ck * 16;
                asm volatile("cp.async.ca.shared.global [%0], [%1], 16;"
                             :: "r"(d), "l"(srcb + (r * 256 + ck * 8) * 2) : "memory");
            }
            asm volatile("cp.async.commit_group;" ::: "memory");
            asm volatile("cp.async.wait_group 1;" ::: "memory");
        } else {
            asm volatile("cp.async.wait_group 0;" ::: "memory");
        }
        __syncthreads();

        const __nv_bfloat16* ws = (const __nv_bfloat16*)(csm + (cur ? WSB_OFF : WSA_OFF));
        const int ch0 = nc * 128;

        float acc[2][8][4];
        #pragma unroll
        for (int mi = 0; mi < 2; ++mi)
            #pragma unroll
            for (int ni = 0; ni < 8; ++ni)
                #pragma unroll
                for (int j = 0; j < 4; ++j) acc[mi][ni][j] = 0.f;

        #pragma unroll 1
        for (int kc = 0; kc < NKS; ++kc) {
            const int k16 = kc * 16;
            u32 a[2][4];
            #pragma unroll
            for (int mi = 0; mi < 2; ++mi) {
                const int tr = tg * 32 + mi * 16 + g;
                const __nv_bfloat16* r0 = hs + tr * SPH + k16 + tig * 2;
                const __nv_bfloat16* r1 = hs + (tr + 8) * SPH + k16 + tig * 2;
                a[mi][0] = *(const u32*)r0;
                a[mi][1] = *(const u32*)r1;
                a[mi][2] = *(const u32*)(r0 + 8);
                a[mi][3] = *(const u32*)(r1 + 8);
            }
            u32 bb[8][2];
            #pragma unroll
            for (int ni = 0; ni < 8; ++ni) {
                const int ch = cg * 64 + ni * 8 + g;
                const __nv_bfloat16* wr = ws + ch * SPH + k16 + tig * 2;
                bb[ni][0] = *(const u32*)wr;
                bb[ni][1] = *(const u32*)(wr + 8);
            }
            #pragma unroll
            for (int mi = 0; mi < 2; ++mi)
                #pragma unroll
                for (int ni = 0; ni < 8; ++ni)
                    mma16816(acc[mi][ni], a[mi], bb[ni]);
        }

        #pragma unroll
        for (int mi = 0; mi < 2; ++mi) {
            #pragma unroll
            for (int ni = 0; ni < 8; ++ni) {
                const int rp = ((ch0 + cg * 64 + ni * 8) >> 1) + tig;
                const u64 c0 = colb + mi * 16;
                g_z[(u64)rp * BT + c0]     = pk2u(__float_as_uint(acc[mi][ni][0]),
                                                  __float_as_uint(acc[mi][ni][1]));
                g_z[(u64)rp * BT + c0 + 8] = pk2u(__float_as_uint(acc[mi][ni][2]),
                                                  __float_as_uint(acc[mi][ni][3]));
            }
        }
    }
}

// ---------------- fused 40-layer WaveNet body: HMMA edition ----------------
#define MS_RS0 0
#define MS_RS1 (513 * RSW * 4)          // 82080
#define MS_W0  (2 * 513 * RSW * 4)      // 164160
#define MS_W1  (MS_W0 + WLW * 4)        // 186176
#define SM1B   (MS_W1 + WLW * 4)        // 208192

__global__ void __launch_bounds__(NT1, 1)
wn_main(const float* __restrict__ x, const float* __restrict__ start_w) {
    extern __shared__ char msm[];
    float* rs0 = (float*)(msm + MS_RS0);
    float* rs1 = (float*)(msm + MS_RS1);

    const int tid = threadIdx.x;
    const int b = blockIdx.y;
    const int t0 = blockIdx.x * TILE1 - HALO;   // time of block row 0

    // init res buffer 0: rs row r (0..512) <-> t = t0 + r - 1 ; row 0 frozen zero
    #pragma unroll 1
    for (int i = tid; i < 513 * 32; i += NT1) {
        int r = i >> 5, c = i & 31;
        int t = t0 + r - 1;
        float xv = (r > 0 && t >= 0 && t < TD) ? x[b * TD + t] : 0.f;
        rs0[r * RSW + c] = start_w[c] * xv;
        if (r == 0) rs1[c] = 0.f;
    }
    // prefetch layer-0 weights
    {
        u32 d0 = smem_u32(msm + MS_W0);
        const char* s0 = (const char*)g_wlay;
        #pragma unroll
        for (int i2 = 0; i2 < 3; ++i2) {
            int idx = tid + i2 * NT1;
            if (idx < WLW / 4)
                asm volatile("cp.async.ca.shared.global [%0], [%1], 16;"
                             :: "r"(d0 + idx * 16), "l"(s0 + idx * 16) : "memory");
        }
        asm volatile("cp.async.commit_group;" ::: "memory");
    }

    const int wid = tid >> 5, lane = tid & 31;
    const int g = lane >> 2, tig = lane & 3;
    const int wr0 = wid * 32;                  // warp's first block row

    #pragma unroll 1
    for (int l = 0; l < NLAY; ++l) {
        __syncthreads();
        const int cur = l & 1;
        const float* rc = cur ? rs1 : rs0;
        float*       rn = cur ? rs0 : rs1;
        const char* wbuf = msm + (cur ? MS_W1 : MS_W0);

        if (l + 1 < NLAY) {
            u32 dn = smem_u32(msm + (cur ? MS_W0 : MS_W1));
            const char* sn = (const char*)(g_wlay + (l + 1) * WLW);
            #pragma unroll
            for (int i2 = 0; i2 < 3; ++i2) {
                int idx = tid + i2 * NT1;
                if (idx < WLW / 4)
                    asm volatile("cp.async.ca.shared.global [%0], [%1], 16;"
                                 :: "r"(dn + idx * 16), "l"(sn + idx * 16) : "memory");
            }
            asm volatile("cp.async.commit_group;" ::: "memory");
            asm volatile("cp.async.wait_group 1;" ::: "memory");
        } else {
            asm volatile("cp.async.wait_group 0;" ::: "memory");
        }
        __syncthreads();

        const __nv_bfloat16* wb1 = (const __nv_bfloat16*)wbuf;              // [64][136]
        const __nv_bfloat16* owb = (const __nv_bfloat16*)(wbuf + WB1_W * 4); // [32][72]

        // ---- accumulators initialized from Z (predicated LDG.64 = fragment pairs) ----
        float acc[2][8][4];
        #pragma unroll
        for (int mi = 0; mi < 2; ++mi) {
            int tA = t0 + wr0 + mi * 16 + g;
            int tB = tA + 8;
            bool vA = (tA >= 0) && (tA < TD);
            bool vB = (tB >= 0) && (tB < TD);
            u64 cA = (u64)b * TD + (vA ? tA : 0);
            u64 cB = (u64)b * TD + (vB ? tB : 0);
            #pragma unroll
            for (int nb = 0; nb < 8; ++nb) {
                const u64* zp = g_z + (u64)(l * 32 + nb * 4 + tig) * BT;
                u64 zA = vA ? zp[cA] : 0ull;
                u64 zB = vB ? zp[cB] : 0ull;
                float2 fa = upk(zA), fb2 = upk(zB);
                acc[mi][nb][0] = fa.x;  acc[mi][nb][1] = fa.y;
                acc[mi][nb][2] = fb2.x; acc[mi][nb][3] = fb2.y;
            }
        }

        // ---- GEMM1: filt+gate conv, 3-term split: hi*Whi + lo*Whi + hi*Wlo ----
        #pragma unroll
        for (int kc = 0; kc < 4; ++kc) {
            const int rowoff = (kc < 2) ? 1 : 0;   // kc0,1: cur (rs row+1); kc2,3: prev
            const int chb = (kc & 1) * 16;
            float2 v[2][4];
            #pragma unroll
            for (int mi = 0; mi < 2; ++mi) {
                int rb = wr0 + mi * 16 + rowoff;
                const float* p0 = rc + (rb + g) * RSW + chb + 2 * tig;
                const float* p1 = rc + (rb + g + 8) * RSW + chb + 2 * tig;
                v[mi][0] = *(const float2*)p0;
                v[mi][1] = *(const float2*)p1;
                v[mi][2] = *(const float2*)(p0 + 8);
                v[mi][3] = *(const float2*)(p1 + 8);
            }
            u32 ah[2][4], al[2][4];
            #pragma unroll
            for (int mi = 0; mi < 2; ++mi)
                #pragma unroll
                for (int s = 0; s < 4; ++s) {
                    ah[mi][s] = bfpack(v[mi][s].x, v[mi][s].y);
                    float hx = __bfloat162float(__float2bfloat16(v[mi][s].x));
                    float hy = __bfloat162float(__float2bfloat16(v[mi][s].y));
                    al[mi][s] = bfpack(v[mi][s].x - hx, v[mi][s].y - hy);
                }
            #pragma unroll
            for (int nb = 0; nb < 8; ++nb) {
                const __nv_bfloat16* wrh = wb1 + (nb * 8 + g) * 136 + kc * 16 + tig * 2;
                u32 bh[2] = { *(const u32*)wrh, *(const u32*)(wrh + 8) };
                const __nv_bfloat16* wrl = wrh + 64;
                u32 bl[2] = { *(const u32*)wrl, *(const u32*)(wrl + 8) };
                mma16816(acc[0][nb], ah[0], bh);   // hi x Whi
                mma16816(acc[1][nb], ah[1], bh);
                mma16816(acc[0][nb], al[0], bh);   // lo x Whi
                mma16816(acc[1][nb], al[1], bh);
                mma16816(acc[0][nb], ah[0], bl);   // hi x Wlo
                mma16816(acc[1][nb], ah[1], bl);
            }
        }

        // ---- activations: fg = tanh(filt) * sig(gate)  (gate = nb+4) ----
        float fg[2][4][4];
        #pragma unroll
        for (int mi = 0; mi < 2; ++mi)
            #pragma unroll
            for (int nb = 0; nb < 4; ++nb)
                #pragma unroll
                for (int j = 0; j < 4; ++j)
                    fg[mi][nb][j] = fast_tanh(acc[mi][nb][j]) * fast_sig(acc[mi][nb + 4][j]);

        // ---- OW GEMM, 3-term split (A register-resident from fg fragments) ----
        float a2[2][4][4];
        #pragma unroll
        for (int mi = 0; mi < 2; ++mi)
            #pragma unroll
            for (int nb = 0; nb < 4; ++nb)
                #pragma unroll
                for (int j = 0; j < 4; ++j) a2[mi][nb][j] = 0.f;

        #pragma unroll
        for (int kc = 0; kc < 2; ++kc) {           // k-chunk of 16 fg channels
            const int fb = kc * 2;                 // fg nb pair {0,1} / {2,3}
            u32 afh[2][4], afl[2][4];
            #pragma unroll
            for (int mi = 0; mi < 2; ++mi)
                #pragma unroll
                for (int hh = 0; hh < 2; ++hh) {
                    float y0 = fg[mi][fb + hh][0], y1 = fg[mi][fb + hh][1];
                    float y2 = fg[mi][fb + hh][2], y3 = fg[mi][fb + hh][3];
                    afh[mi][hh * 2]     = bfpack(y0, y1);
                    afh[mi][hh * 2 + 1] = bfpack(y2, y3);
                    float l0 = y0 - __bfloat162float(__float2bfloat16(y0));
                    float l1 = y1 - __bfloat162float(__float2bfloat16(y1));
                    float l2 = y2 - __bfloat162float(__float2bfloat16(y2));
                    float l3 = y3 - __bfloat162float(__float2bfloat16(y3));
                    afl[mi][hh * 2]     = bfpack(l0, l1);
                    afl[mi][hh * 2 + 1] = bfpack(l2, l3);
                }
            #pragma unroll
            for (int nb = 0; nb < 4; ++nb) {
                const __nv_bfloat16* wrh = owb + (nb * 8 + g) * 72 + kc * 16 + tig * 2;
                u32 bh[2] = { *(const u32*)wrh, *(const u32*)(wrh + 8) };
                const __nv_bfloat16* wrl = wrh + 32;
                u32 bl[2] = { *(const u32*)wrl, *(const u32*)(wrl + 8) };
                mma16816(a2[0][nb], afh[0], bh);   // hi x Whi
                mma16816(a2[1][nb], afh[1], bh);
                mma16816(a2[0][nb], afl[0], bh);   // lo x Whi
                mma16816(a2[1][nb], afl[1], bh);
                mma16816(a2[0][nb], afh[0], bl);   // hi x Wlo
                mma16816(a2[1][nb], afh[1], bl);
            }
        }

        // ---- residual update into next buffer (own rows only) ----
        #pragma unroll
        for (int mi = 0; mi < 2; ++mi)
            #pragma unroll
            for (int nb = 0; nb < 4; ++nb) {
                int rr = wr0 + mi * 16 + g + 1;
                int ch = nb * 8 + tig * 2;
                float2 d0 = *(const float2*)(rc + rr * RSW + ch);
                float2 d1 = *(const float2*)(rc + (rr + 8) * RSW + ch);
                d0.x += a2[mi][nb][0]; d0.y += a2[mi][nb][1];
                d1.x += a2[mi][nb][2]; d1.y += a2[mi][nb][3];
                *(float2*)(rn + rr * RSW + ch) = d0;
                *(float2*)(rn + (rr + 8) * RSW + ch) = d1;
            }
    }

    // layer 39 wrote rs0. skip = res_final - start_w*x
    __syncthreads();
    {
        int t = t0 + tid;
        if (tid >= HALO && t < TD) {
            float xv = x[b * TD + t];
            #pragma unroll 1
            for (int c = 0; c < RCD; ++c)
                g_skips[(b * RCD + c) * TD + t] = rs0[(tid + 1) * RSW + c] - start_w[c] * xv;
        }
    }
}

// ---------------- end stack: relu -> 256x32 (fp32) -> relu -> 256x256 (HMMA) ----------------
#define E_S_OFF  0
#define E_W1_OFF 8192
#define E_EB_OFF 40960
#define E_W2_OFF 140288
#define CSM3     209920

__global__ void __launch_bounds__(512, 1)
wn_end(float* __restrict__ out) {
    extern __shared__ char esm[];
    float* s_s  = (float*)(esm + E_S_OFF);
    float* w1_s = (float*)(esm + E_W1_OFF);
    __nv_bfloat16* eb = (__nv_bfloat16*)(esm + E_EB_OFF);
    __nv_bfloat16* w2 = (__nv_bfloat16*)(esm + E_W2_OFF);
    float* D_s  = (float*)(esm + E_EB_OFF);

    const int tid = threadIdx.x;
    const int b = blockIdx.y;
    const int t0 = blockIdx.x * ET;

    #pragma unroll 1
    for (int i = tid; i < RCD * ET; i += 512) {
        int c = i >> 6, t = i & 63;
        s_s[i] = fmaxf(g_skips[(b * RCD + c) * TD + t0 + t], 0.f);
    }
    #pragma unroll 1
    for (int i = tid; i < RCD * SCD; i += 512) w1_s[i] = g_e1[i];
    __syncthreads();

    {
        const int tc = tid & 63, ocg = tid >> 6;
        u64 acc1[16];
        #pragma unroll
        for (int p = 0; p < 16; ++p) acc1[p] = 0ull;
        #pragma unroll 4
        for (int c = 0; c < RCD; ++c) {
            u64 v2 = pk2(s_s[c * 64 + tc]);
            const ulonglong2* wr = (const ulonglong2*)(w1_s + c * SCD + ocg * 32);
            #pragma unroll
            for (int q = 0; q < 8; ++q) {
                ulonglong2 a = wr[q];
                fma2(acc1[2 * q], a.x, v2); fma2(acc1[2 * q + 1], a.y, v2);
            }
        }
        __nv_bfloat16* row = eb + tc * EBS;
        #pragma unroll
        for (int p = 0; p < 16; ++p) {
            float2 v = upk(acc1[p]);
            float e0 = fmaxf(v.x, 0.f), e1v = fmaxf(v.y, 0.f);
            float h0 = __bfloat162float(__float2bfloat16(e0));
            float h1 = __bfloat162float(__float2bfloat16(e1v));
            u32 hip = bfpack(e0, e1v);
            u32 lop = bfpack(e0 - h0, e1v - h1);
            int ch = ocg * 32 + 2 * p;
            *(u32*)(row + ch)       = hip;
            *(u32*)(row + 256 + ch) = lop;
            *(u32*)(row + 512 + ch) = hip;
        }
    }

    const int wid = tid >> 5, lane = tid & 31;
    const int tg = wid >> 2, cg = wid & 3;
    const int g = lane >> 2, tig = lane & 3;

    float acc[8][4];
    #pragma unroll
    for (int ni = 0; ni < 8; ++ni)
        #pragma unroll
        for (int j = 0; j < 4; ++j) acc[ni][j] = 0.f;

    const u32 w2u = smem_u32(w2);
    #pragma unroll 1
    for (int kc = 0; kc < 6; ++kc) {
        __syncthreads();
        #pragma unroll
        for (int j = 0; j < 8; ++j) {
            int idx = tid + j * 512;
            int r = idx >> 4, sg = idx & 15;
            u32 d = w2u + r * 272 + sg * 16;
            const char* s = (const char*)g_e2b + (r * EKS + kc * 128 + sg * 8) * 2;
            asm volatile("cp.async.ca.shared.global [%0], [%1], 16;"
                         :: "r"(d), "l"(s) : "memory");
        }
        asm volatile("cp.async.commit_group;" ::: "memory");
        asm volatile("cp.async.wait_group 0;" ::: "memory");
        __syncthreads();

        #pragma unroll
        for (int ks = 0; ks < 8; ++ks) {
            const int kg = kc * 128 + ks * 16;
            const __nv_bfloat16* r0 = eb + (tg * 16 + g) * EBS + kg + tig * 2;
            const __nv_bfloat16* r1 = r0 + 8 * EBS;
            u32 a[4];
            a[0] = *(const u32*)r0;
            a[1] = *(const u32*)r1;
            a[2] = *(const u32*)(r0 + 8);
            a[3] = *(const u32*)(r1 + 8);
            #pragma unroll
            for (int ni = 0; ni < 8; ++ni) {
                const int ch = cg * 64 + ni * 8 + g;
                const __nv_bfloat16* wr = w2 + ch * 136 + ks * 16 + tig * 2;
                u32 bb[2];
                bb[0] = *(const u32*)wr;
                bb[1] = *(const u32*)(wr + 8);
                mma16816(acc[ni], a, bb);
            }
        }
    }

    __syncthreads();
    #pragma unroll
    for (int ni = 0; ni < 8; ++ni) {
        const int ch = cg * 64 + ni * 8 + tig * 2;
        const int tt = tg * 16 + g;
        D_s[ch * 65 + tt]           = acc[ni][0];
        D_s[(ch + 1) * 65 + tt]     = acc[ni][1];
        D_s[ch * 65 + tt + 8]       = acc[ni][2];
        D_s[(ch + 1) * 65 + tt + 8] = acc[ni][3];
    }
    __syncthreads();

    #pragma unroll 1
    for (int i = tid; i < NCLS * ET; i += 512) {
        int ch = i >> 6, t = i & 63;
        out[(b * NCLS + ch) * TD + t0 + t] = D_s[ch * 65 + t];
    }
}

// ---------------- launch ----------------
extern "C" void kernel_launch(void* const* d_in, const int* in_sizes, int n_in,
                              void* d_out, int out_size) {
    const float* x       = (const float*)d_in[0];
    const float* h       = (const float*)d_in[1];
    const float* start_w = (const float*)d_in[2];
    const float* dil_w   = (const float*)d_in[3];
    const float* f_w     = (const float*)d_in[4];
    const float* g_w     = (const float*)d_in[5];
    const float* cf_w    = (const float*)d_in[6];
    const float* cg_w    = (const float*)d_in[7];
    const float* out_w   = (const float*)d_in[8];
    const float* e1_w    = (const float*)d_in[9];
    const float* e2_w    = (const float*)d_in[10];
    float* out = (float*)d_out;

    cudaFuncSetAttribute(wn_cond, cudaFuncAttributeMaxDynamicSharedMemorySize, CSM2);
    cudaFuncSetAttribute(wn_main, cudaFuncAttributeMaxDynamicSharedMemorySize, SM1B);
    cudaFuncSetAttribute(wn_end,  cudaFuncAttributeMaxDynamicSharedMemorySize, CSM3);

    wn_pack<<<256, 256>>>(dil_w, f_w, g_w, cf_w, cg_w, out_w, e1_w, e2_w);
    wn_cond<<<512, 256, CSM2>>>(h);
    wn_main<<<dim3(NTILES, BD), NT1, SM1B>>>(x, start_w);
    wn_end<<<dim3(TD / ET, BD), 512, CSM3>>>(out);
}

// round 17
// speedup vs baseline: 2.4523x; 1.0218x over previous
#include <cuda_runtime.h>
#include <cuda_bf16.h>

// ---------------- dims ----------------
#define BD 4
#define TD 16384
#define BT (BD * TD)     // 65536 time-batch columns
#define RCD 32
#define SCD 256
#define NCLS 256
#define NCOND 80
#define NLAY 40

// main kernel tiling: 512 threads = 16 warps x 32 time rows, single wave (140 blocks)
#define NT1 512
#define HALO 40
#define TILE1 472
#define NTILES 35

// cond GEMM (mma.sync bf16): K = 240 (Whi|Whi|Wlo  x  hhi|hlo|hhi), 15 k-steps
#define NKS 15
#define SPH 248          // bf16 row stride (words%32 = 28 -> conflict-free)
#define NCHT 20          // 2560 channels / 128 per tile

// end kernel tiling (HMMA e2)
#define ET 64
#define EKS 768
#define EBS 776

// main HMMA layer-weight pack (u32 words)
#define WB1_W 4352       // conv B tile: 64 ch x 136 bf16 (128 k + 8 pad) = 4352 u32
#define OWB_W 1152       // OW  B tile: 32 n  x 72 bf16  (64 k + 8 pad)  = 1152 u32
#define WLW   (WB1_W + OWB_W)   // 5504 u32 per layer
#define RSW   40         // fp32 residual row stride (8g+2tig -> conflict-free LDS.64)

// ---------------- device scratch (static, no allocation) ----------------
__device__ __align__(16) unsigned int g_wlay[NLAY * WLW];   // main layer weights bf16-split
__device__ __align__(16) __nv_bfloat16 g_wb[2560 * 256];    // cond weights bf16 split
__device__ float g_e1[RCD * SCD];
__device__ __align__(16) __nv_bfloat16 g_e2b[NCLS * EKS];   // e2 weights bf16 split
__device__ float g_skips[BD * RCD * TD];
__device__ unsigned long long g_z[1280ull * BT];            // cond pre-activations (f32 pairs)

// ---------------- helpers ----------------
typedef unsigned long long u64;
typedef unsigned int u32;

__device__ __forceinline__ u64 pk2(float v) {
    u64 r;
    asm("mov.b64 %0, {%1, %2};" : "=l"(r) : "f"(v), "f"(v));
    return r;
}
__device__ __forceinline__ u64 pk2u(u32 lo, u32 hi) {
    u64 r;
    asm("mov.b64 %0, {%1, %2};" : "=l"(r) : "r"(lo), "r"(hi));
    return r;
}
__device__ __forceinline__ void fma2(u64 &d, u64 a, u64 b) {
    asm("fma.rn.f32x2 %0, %1, %2, %0;" : "+l"(d) : "l"(a), "l"(b));
}
__device__ __forceinline__ float2 upk(u64 v) {
    float2 r;
    asm("mov.b64 {%0, %1}, %2;" : "=f"(r.x), "=f"(r.y) : "l"(v));
    return r;
}
__device__ __forceinline__ u32 smem_u32(const void* p) {
    u32 a;
    asm("{ .reg .u64 t; cvta.to.shared.u64 t, %1; cvt.u32.u64 %0, t; }" : "=r"(a) : "l"(p));
    return a;
}
__device__ __forceinline__ u32 bfpack(float a, float b) {
    u32 r;
    asm("cvt.rn.bf16x2.f32 %0, %1, %2;" : "=r"(r) : "f"(b), "f"(a));
    return r;
}

__device__ __forceinline__ float fast_tanh(float x) {
    float a = fminf(fmaxf(-2.f * x, -60.f), 60.f);
    float e = __expf(a);
    return (1.f - e) * __fdividef(1.f, 1.f + e);
}
__device__ __forceinline__ float fast_sig(float x) {
    float a = fminf(fmaxf(-x, -60.f), 60.f);
    float e = __expf(a);
    return __fdividef(1.f, 1.f + e);
}

// warp-level bf16 MMA: D(16x8,f32) += A(16x16,row) * B(16x8,col)
__device__ __forceinline__ void mma16816(float* c, const u32* a, const u32* b) {
    asm volatile(
        "mma.sync.aligned.m16n8k16.row.col.f32.bf16.bf16.f32 "
        "{%0,%1,%2,%3}, {%4,%5,%6,%7}, {%8,%9}, {%0,%1,%2,%3};"
        : "+f"(c[0]), "+f"(c[1]), "+f"(c[2]), "+f"(c[3])
        : "r"(a[0]), "r"(a[1]), "r"(a[2]), "r"(a[3]), "r"(b[0]), "r"(b[1]));
}
// ldmatrix x4 (b16, non-transposed)
__device__ __forceinline__ void ldm4(u32& r0, u32& r1, u32& r2, u32& r3, u32 addr) {
    asm volatile("ldmatrix.sync.aligned.m8n8.x4.shared.b16 {%0,%1,%2,%3}, [%4];"
        : "=r"(r0), "=r"(r1), "=r"(r2), "=r"(r3) : "r"(addr));
}

// ---------------- pack helpers ----------------
__device__ float wl1val(const float* f_w, const float* g_w, const float* dil_w,
                        int l, int ch, int kk) {
    if (kk >= 128) return 0.f;
    int sub = kk >> 5, c = kk & 31;
    int dk = (sub & 1) ? 0 : 1;
    const float* base = (ch < 32) ? f_w + (l * 32 + ch) * 32
                                  : g_w + (l * 32 + (ch - 32)) * 32;
    float s = 0.f;
    #pragma unroll 8
    for (int d = 0; d < 32; ++d)
        s += base[d] * dil_w[((l * 32 + d) * 32 + c) * 2 + dk];
    if (sub < 2) return s;
    return s - __bfloat162float(__float2bfloat16(s));
}
__device__ float owval(const float* out_w, int l, int n, int kk) {
    if (kk >= 64) return 0.f;
    float v = out_w[(l * 32 + n) * 32 + (kk & 31)];
    if (kk < 32) return v;
    return v - __bfloat162float(__float2bfloat16(v));
}

// ---------------- weight repack + compose kernel ----------------
__global__ void wn_pack(const float* __restrict__ dil_w, const float* __restrict__ f_w,
                        const float* __restrict__ g_w,   const float* __restrict__ cf_w,
                        const float* __restrict__ cg_w,  const float* __restrict__ out_w,
                        const float* __restrict__ e1_w,  const float* __restrict__ e2_w) {
    int stride = gridDim.x * blockDim.x;
    int tid0 = blockIdx.x * blockDim.x + threadIdx.x;

    for (int i = tid0; i < NLAY * WLW; i += stride) {
        int l = i / WLW, p = i % WLW;
        float v0, v1;
        if (p < WB1_W) {
            int ch = p / 68, wi = p % 68;
            v0 = wl1val(f_w, g_w, dil_w, l, ch, wi * 2);
            v1 = wl1val(f_w, g_w, dil_w, l, ch, wi * 2 + 1);
        } else {
            int q = p - WB1_W;
            int n = q / 36, wi = q % 36;
            v0 = owval(out_w, l, n, wi * 2);
            v1 = owval(out_w, l, n, wi * 2 + 1);
        }
        g_wlay[i] = bfpack(v0, v1);
    }
    for (int j = tid0; j < 2560 * 256; j += stride) {
        int r = j >> 8, k = j & 255;
        int l = r >> 6, ch = r & 63;
        const float* src = (ch < 32) ? cf_w + (l * 32 + ch) * NCOND
                                     : cg_w + (l * 32 + (ch - 32)) * NCOND;
        __nv_bfloat16 o;
        if (k < 80) {
            o = __float2bfloat16(src[k]);
        } else if (k < 160) {
            o = __float2bfloat16(src[k - 80]);
        } else if (k < 240) {
            float w = src[k - 160];
            __nv_bfloat16 hi = __float2bfloat16(w);
            o = __float2bfloat16(w - __bfloat162float(hi));
        } else {
            o = __float2bfloat16(0.f);
        }
        g_wb[j] = o;
    }
    for (int j = tid0; j < RCD * SCD; j += stride) {
        int c = j >> 8, s = j & 255;
        g_e1[j] = e1_w[s * RCD + c];
    }
    for (int j = tid0; j < NCLS * EKS; j += stride) {
        int o = j / EKS, k = j % EKS;
        float w = e2_w[o * SCD + (k & 255)];
        __nv_bfloat16 hi = __float2bfloat16(w);
        g_e2b[j] = (k < 512) ? hi : __float2bfloat16(w - __bfloat162float(hi));
    }
}

// ---------------- cond GEMM: Z = Wc @ h, bf16-split mma.sync + ldmatrix ----------------
#define HS_OFF  0
#define WSA_OFF (128 * SPH * 2)
#define WSB_OFF (WSA_OFF + 128 * SPH * 2)
#define FB_OFF  WSA_OFF
#define CSM2    (WSB_OFF + 128 * SPH * 2)

__global__ void __launch_bounds__(256, 1)
wn_cond(const float* __restrict__ h) {
    extern __shared__ char csm[];
    __nv_bfloat16* hs = (__nv_bfloat16*)(csm + HS_OFF);
    float* fbuf = (float*)(csm + FB_OFF);

    const int tid = threadIdx.x;
    const int b = blockIdx.x >> 7;
    const int t0 = (blockIdx.x & 127) << 7;

    #pragma unroll 1
    for (int idx = tid; idx < NCOND * 128; idx += 256) {
        int c = idx >> 7, t = idx & 127;
        fbuf[c * 129 + t] = h[(b * NCOND + c) * TD + t0 + t];
    }
    __syncthreads();
    #pragma unroll 1
    for (int idx = tid; idx < NCOND * 128; idx += 256) {
        int t = idx / NCOND, c = idx % NCOND;
        float hv = fbuf[c * 129 + t];
        __nv_bfloat16 hi = __float2bfloat16(hv);
        __nv_bfloat16 lo = __float2bfloat16(hv - __bfloat162float(hi));
        __nv_bfloat16* row = hs + t * SPH;
        row[c] = hi;
        row[c + 80] = lo;
        row[c + 160] = hi;
    }
    __syncthreads();

    const u32 ws_s[2] = { smem_u32(csm + WSA_OFF), smem_u32(csm + WSB_OFF) };

    {
        const char* srcb = (const char*)g_wb;
        #pragma unroll 1
        for (int i2 = 0; i2 < 15; ++i2) {
            int idx = tid + i2 * 256;
            int r = idx / 30, ck = idx % 30;
            u32 d = ws_s[0] + r * (SPH * 2) + ck * 16;
            asm volatile("cp.async.ca.shared.global [%0], [%1], 16;"
                         :: "r"(d), "l"(srcb + (r * 256 + ck * 8) * 2) : "memory");
        }
        asm volatile("cp.async.commit_group;" ::: "memory");
    }

    const int wid = tid >> 5, lane = tid & 31;
    const int tg = wid >> 1, cg = wid & 1;
    const int g = lane >> 2, tig = lane & 3;
    const u64 colb = (u64)blockIdx.x * 128 + tg * 32 + g;

    // ldmatrix lane-address components (bytes)
    const int lrow8 = (lane & 7) + ((lane >> 3) & 1) * 8;  // row within 16-row group
    const int lkoff = (lane >> 4) * 8;                     // k half (elements)
    // A addresses for mi=0,1 (k advances by 32B per k-step)
    u32 aAddr[2];
    #pragma unroll
    for (int mi = 0; mi < 2; ++mi) {
        int tr = tg * 32 + mi * 16 + lrow8;
        aAddr[mi] = smem_u32(hs + tr * SPH + lkoff);
    }
    // B address row components: ni = 2p + (lane>>4), rows of ws tile
    int brow[4];
    #pragma unroll
    for (int p = 0; p < 4; ++p)
        brow[p] = (cg * 64 + (2 * p + (lane >> 4)) * 8 + (lane & 7)) * (SPH * 2)
                  + ((lane >> 3) & 1) * 16;   // k half in bytes

    #pragma unroll 1
    for (int nc = 0; nc < NCHT; ++nc) {
        const int cur = nc & 1;
        __syncthreads();

        if (nc + 1 < NCHT) {
            const char* srcb = (const char*)(g_wb + (u64)(nc + 1) * 128 * 256);
            #pragma unroll 1
            for (int i2 = 0; i2 < 15; ++i2) {
                int idx = tid + i2 * 256;
                int r = idx / 30, ck = idx % 30;
                u32 d = ws_s[cur ^ 1] + r * (SPH * 2) + ck * 16;
                asm volatile("cp.async.ca.shared.global [%0], [%1], 16;"
                             :: "r"(d), "l"(srcb + (r * 256 + ck * 8) * 2) : "memory");
            }
            asm volatile("cp.async.commit_group;" ::: "memory");
            asm volatile("cp.async.wait_group 1;" ::: "memory");
        } else {
            asm volatile("cp.async.wait_group 0;" ::: "memory");
        }
        __syncthreads();

        const u32 wsb = ws_s[cur];
        const int ch0 = nc * 128;

        float acc[2][8][4];
        #pragma unroll
        for (int mi = 0; mi < 2; ++mi)
            #pragma unroll
            for (int ni = 0; ni < 8; ++ni)
                #pragma unroll
                for (int j = 0; j < 4; ++j) acc[mi][ni][j] = 0.f;

        #pragma unroll 3
        for (int kc = 0; kc < NKS; ++kc) {
            const u32 kb = kc * 32;        // byte advance per k-step
            u32 a[2][4];
            ldm4(a[0][0], a[0][1], a[0][2], a[0][3], aAddr[0] + kb);
            ldm4(a[1][0], a[1][1], a[1][2], a[1][3], aAddr[1] + kb);
            u32 bb[8][2];
            #pragma unroll
            for (int p = 0; p < 4; ++p) {
                u32 q0, q1, q2, q3;
                ldm4(q0, q1, q2, q3, wsb + brow[p] + kb);
                bb[2 * p][0] = q0;     bb[2 * p][1] = q1;
                bb[2 * p + 1][0] = q2; bb[2 * p + 1][1] = q3;
            }
            #pragma unroll
            for (int mi = 0; mi < 2; ++mi)
                #pragma unroll
                for (int ni = 0; ni < 8; ++ni)
                    mma16816(acc[mi][ni], a[mi], bb[ni]);
        }

        #pragma unroll
        for (int mi = 0; mi < 2; ++mi) {
            #pragma unroll
            for (int ni = 0; ni < 8; ++ni) {
                const int rp = ((ch0 + cg * 64 + ni * 8) >> 1) + tig;
                const u64 c0 = colb + mi * 16;
                g_z[(u64)rp * BT + c0]     = pk2u(__float_as_uint(acc[mi][ni][0]),
                                                  __float_as_uint(acc[mi][ni][1]));
                g_z[(u64)rp * BT + c0 + 8] = pk2u(__float_as_uint(acc[mi][ni][2]),
                                                  __float_as_uint(acc[mi][ni][3]));
            }
        }
    }
}

// ---------------- fused 40-layer WaveNet body: HMMA edition (unchanged) ----------------
#define MS_RS0 0
#define MS_RS1 (513 * RSW * 4)          // 82080
#define MS_W0  (2 * 513 * RSW * 4)      // 164160
#define MS_W1  (MS_W0 + WLW * 4)        // 186176
#define SM1B   (MS_W1 + WLW * 4)        // 208192

__global__ void __launch_bounds__(NT1, 1)
wn_main(const float* __restrict__ x, const float* __restrict__ start_w) {
    extern __shared__ char msm[];
    float* rs0 = (float*)(msm + MS_RS0);
    float* rs1 = (float*)(msm + MS_RS1);

    const int tid = threadIdx.x;
    const int b = blockIdx.y;
    const int t0 = blockIdx.x * TILE1 - HALO;   // time of block row 0

    #pragma unroll 1
    for (int i = tid; i < 513 * 32; i += NT1) {
        int r = i >> 5, c = i & 31;
        int t = t0 + r - 1;
        float xv = (r > 0 && t >= 0 && t < TD) ? x[b * TD + t] : 0.f;
        rs0[r * RSW + c] = start_w[c] * xv;
        if (r == 0) rs1[c] = 0.f;
    }
    {
        u32 d0 = smem_u32(msm + MS_W0);
        const char* s0 = (const char*)g_wlay;
        #pragma unroll
        for (int i2 = 0; i2 < 3; ++i2) {
            int idx = tid + i2 * NT1;
            if (idx < WLW / 4)
                asm volatile("cp.async.ca.shared.global [%0], [%1], 16;"
                             :: "r"(d0 + idx * 16), "l"(s0 + idx * 16) : "memory");
        }
        asm volatile("cp.async.commit_group;" ::: "memory");
    }

    const int wid = tid >> 5, lane = tid & 31;
    const int g = lane >> 2, tig = lane & 3;
    const int wr0 = wid * 32;

    #pragma unroll 1
    for (int l = 0; l < NLAY; ++l) {
        __syncthreads();
        const int cur = l & 1;
        const float* rc = cur ? rs1 : rs0;
        float*       rn = cur ? rs0 : rs1;
        const char* wbuf = msm + (cur ? MS_W1 : MS_W0);

        if (l + 1 < NLAY) {
            u32 dn = smem_u32(msm + (cur ? MS_W0 : MS_W1));
            const char* sn = (const char*)(g_wlay + (l + 1) * WLW);
            #pragma unroll
            for (int i2 = 0; i2 < 3; ++i2) {
                int idx = tid + i2 * NT1;
                if (idx < WLW / 4)
                    asm volatile("cp.async.ca.shared.global [%0], [%1], 16;"
                                 :: "r"(dn + idx * 16), "l"(sn + idx * 16) : "memory");
            }
            asm volatile("cp.async.commit_group;" ::: "memory");
            asm volatile("cp.async.wait_group 1;" ::: "memory");
        } else {
            asm volatile("cp.async.wait_group 0;" ::: "memory");
        }
        __syncthreads();

        const __nv_bfloat16* wb1 = (const __nv_bfloat16*)wbuf;
        const __nv_bfloat16* owb = (const __nv_bfloat16*)(wbuf + WB1_W * 4);

        float acc[2][8][4];
        #pragma unroll
        for (int mi = 0; mi < 2; ++mi) {
            int tA = t0 + wr0 + mi * 16 + g;
            int tB = tA + 8;
            bool vA = (tA >= 0) && (tA < TD);
            bool vB = (tB >= 0) && (tB < TD);
            u64 cA = (u64)b * TD + (vA ? tA : 0);
            u64 cB = (u64)b * TD + (vB ? tB : 0);
            #pragma unroll
            for (int nb = 0; nb < 8; ++nb) {
                const u64* zp = g_z + (u64)(l * 32 + nb * 4 + tig) * BT;
                u64 zA = vA ? zp[cA] : 0ull;
                u64 zB = vB ? zp[cB] : 0ull;
                float2 fa = upk(zA), fb2 = upk(zB);
                acc[mi][nb][0] = fa.x;  acc[mi][nb][1] = fa.y;
                acc[mi][nb][2] = fb2.x; acc[mi][nb][3] = fb2.y;
            }
        }

        #pragma unroll
        for (int kc = 0; kc < 4; ++kc) {
            const int rowoff = (kc < 2) ? 1 : 0;
            const int chb = (kc & 1) * 16;
            float2 v[2][4];
            #pragma unroll
            for (int mi = 0; mi < 2; ++mi) {
                int rb = wr0 + mi * 16 + rowoff;
                const float* p0 = rc + (rb + g) * RSW + chb + 2 * tig;
                const float* p1 = rc + (rb + g + 8) * RSW + chb + 2 * tig;
                v[mi][0] = *(const float2*)p0;
                v[mi][1] = *(const float2*)p1;
                v[mi][2] = *(const float2*)(p0 + 8);
                v[mi][3] = *(const float2*)(p1 + 8);
            }
            u32 ah[2][4], al[2][4];
            #pragma unroll
            for (int mi = 0; mi < 2; ++mi)
                #pragma unroll
                for (int s = 0; s < 4; ++s) {
                    ah[mi][s] = bfpack(v[mi][s].x, v[mi][s].y);
                    float hx = __bfloat162float(__float2bfloat16(v[mi][s].x));
                    float hy = __bfloat162float(__float2bfloat16(v[mi][s].y));
                    al[mi][s] = bfpack(v[mi][s].x - hx, v[mi][s].y - hy);
                }
            #pragma unroll
            for (int nb = 0; nb < 8; ++nb) {
                const __nv_bfloat16* wrh = wb1 + (nb * 8 + g) * 136 + kc * 16 + tig * 2;
                u32 bh[2] = { *(const u32*)wrh, *(const u32*)(wrh + 8) };
                const __nv_bfloat16* wrl = wrh + 64;
                u32 bl[2] = { *(const u32*)wrl, *(const u32*)(wrl + 8) };
                mma16816(acc[0][nb], ah[0], bh);
                mma16816(acc[1][nb], ah[1], bh);
                mma16816(acc[0][nb], al[0], bh);
                mma16816(acc[1][nb], al[1], bh);
                mma16816(acc[0][nb], ah[0], bl);
                mma16816(acc[1][nb], ah[1], bl);
            }
        }

        float fg[2][4][4];
        #pragma unroll
        for (int mi = 0; mi < 2; ++mi)
            #pragma unroll
            for (int nb = 0; nb < 4; ++nb)
                #pragma unroll
                for (int j = 0; j < 4; ++j)
                    fg[mi][nb][j] = fast_tanh(acc[mi][nb][j]) * fast_sig(acc[mi][nb + 4][j]);

        float a2[2][4][4];
        #pragma unroll
        for (int mi = 0; mi < 2; ++mi)
            #pragma unroll
            for (int nb = 0; nb < 4; ++nb)
                #pragma unroll
                for (int j = 0; j < 4; ++j) a2[mi][nb][j] = 0.f;

        #pragma unroll
        for (int kc = 0; kc < 2; ++kc) {
            const int fb = kc * 2;
            u32 afh[2][4], afl[2][4];
            #pragma unroll
            for (int mi = 0; mi < 2; ++mi)
                #pragma unroll
                for (int hh = 0; hh < 2; ++hh) {
                    float y0 = fg[mi][fb + hh][0], y1 = fg[mi][fb + hh][1];
                    float y2 = fg[mi][fb + hh][2], y3 = fg[mi][fb + hh][3];
                    afh[mi][hh * 2]     = bfpack(y0, y1);
                    afh[mi][hh * 2 + 1] = bfpack(y2, y3);
                    float l0 = y0 - __bfloat162float(__float2bfloat16(y0));
                    float l1 = y1 - __bfloat162float(__float2bfloat16(y1));
                    float l2 = y2 - __bfloat162float(__float2bfloat16(y2));
                    float l3 = y3 - __bfloat162float(__float2bfloat16(y3));
                    afl[mi][hh * 2]     = bfpack(l0, l1);
                    afl[mi][hh * 2 + 1] = bfpack(l2, l3);
                }
            #pragma unroll
            for (int nb = 0; nb < 4; ++nb) {
                const __nv_bfloat16* wrh = owb + (nb * 8 + g) * 72 + kc * 16 + tig * 2;
                u32 bh[2] = { *(const u32*)wrh, *(const u32*)(wrh + 8) };
                const __nv_bfloat16* wrl = wrh + 32;
                u32 bl[2] = { *(const u32*)wrl, *(const u32*)(wrl + 8) };
                mma16816(a2[0][nb], afh[0], bh);
                mma16816(a2[1][nb], afh[1], bh);
                mma16816(a2[0][nb], afl[0], bh);
                mma16816(a2[1][nb], afl[1], bh);
                mma16816(a2[0][nb], afh[0], bl);
                mma16816(a2[1][nb], afh[1], bl);
            }
        }

        #pragma unroll
        for (int mi = 0; mi < 2; ++mi)
            #pragma unroll
            for (int nb = 0; nb < 4; ++nb) {
                int rr = wr0 + mi * 16 + g + 1;
                int ch = nb * 8 + tig * 2;
                float2 d0 = *(const float2*)(rc + rr * RSW + ch);
                float2 d1 = *(const float2*)(rc + (rr + 8) * RSW + ch);
                d0.x += a2[mi][nb][0]; d0.y += a2[mi][nb][1];
                d1.x += a2[mi][nb][2]; d1.y += a2[mi][nb][3];
                *(float2*)(rn + rr * RSW + ch) = d0;
                *(float2*)(rn + (rr + 8) * RSW + ch) = d1;
            }
    }

    __syncthreads();
    {
        int t = t0 + tid;
        if (tid >= HALO && t < TD) {
            float xv = x[b * TD + t];
            #pragma unroll 1
            for (int c = 0; c < RCD; ++c)
                g_skips[(b * RCD + c) * TD + t] = rs0[(tid + 1) * RSW + c] - start_w[c] * xv;
        }
    }
}

// ---------------- end stack: relu -> 256x32 (fp32) -> relu -> 256x256 (HMMA) ----------------
#define E_S_OFF  0
#define E_W1_OFF 8192
#define E_EB_OFF 40960
#define E_W2_OFF 140288
#define CSM3     209920

__global__ void __launch_bounds__(512, 1)
wn_end(float* __restrict__ out) {
    extern __shared__ char esm[];
    float* s_s  = (float*)(esm + E_S_OFF);
    float* w1_s = (float*)(esm + E_W1_OFF);
    __nv_bfloat16* eb = (__nv_bfloat16*)(esm + E_EB_OFF);
    __nv_bfloat16* w2 = (__nv_bfloat16*)(esm + E_W2_OFF);
    float* D_s  = (float*)(esm + E_EB_OFF);

    const int tid = threadIdx.x;
    const int b = blockIdx.y;
    const int t0 = blockIdx.x * ET;

    #pragma unroll 1
    for (int i = tid; i < RCD * ET; i += 512) {
        int c = i >> 6, t = i & 63;
        s_s[i] = fmaxf(g_skips[(b * RCD + c) * TD + t0 + t], 0.f);
    }
    #pragma unroll 1
    for (int i = tid; i < RCD * SCD; i += 512) w1_s[i] = g_e1[i];
    __syncthreads();

    {
        const int tc = tid & 63, ocg = tid >> 6;
        u64 acc1[16];
        #pragma unroll
        for (int p = 0; p < 16; ++p) acc1[p] = 0ull;
        #pragma unroll 4
        for (int c = 0; c < RCD; ++c) {
            u64 v2 = pk2(s_s[c * 64 + tc]);
            const ulonglong2* wr = (const ulonglong2*)(w1_s + c * SCD + ocg * 32);
            #pragma unroll
            for (int q = 0; q < 8; ++q) {
                ulonglong2 a = wr[q];
                fma2(acc1[2 * q], a.x, v2); fma2(acc1[2 * q + 1], a.y, v2);
            }
        }
        __nv_bfloat16* row = eb + tc * EBS;
        #pragma unroll
        for (int p = 0; p < 16; ++p) {
            float2 v = upk(acc1[p]);
            float e0 = fmaxf(v.x, 0.f), e1v = fmaxf(v.y, 0.f);
            float h0 = __bfloat162float(__float2bfloat16(e0));
            float h1 = __bfloat162float(__float2bfloat16(e1v));
            u32 hip = bfpack(e0, e1v);
            u32 lop = bfpack(e0 - h0, e1v - h1);
            int ch = ocg * 32 + 2 * p;
            *(u32*)(row + ch)       = hip;
            *(u32*)(row + 256 + ch) = lop;
            *(u32*)(row + 512 + ch) = hip;
        }
    }

    const int wid = tid >> 5, lane = tid & 31;
    const int tg = wid >> 2, cg = wid & 3;
    const int g = lane >> 2, tig = lane & 3;

    float acc[8][4];
    #pragma unroll
    for (int ni = 0; ni < 8; ++ni)
        #pragma unroll
        for (int j = 0; j < 4; ++j) acc[ni][j] = 0.f;

    const u32 w2u = smem_u32(w2);
    #pragma unroll 1
    for (int kc = 0; kc < 6; ++kc) {
        __syncthreads();
        #pragma unroll
        for (int j = 0; j < 8; ++j) {
            int idx = tid + j * 512;
            int r = idx >> 4, sg = idx & 15;
            u32 d = w2u + r * 272 + sg * 16;
            const char* s = (const char*)g_e2b + (r * EKS + kc * 128 + sg * 8) * 2;
            asm volatile("cp.async.ca.shared.global [%0], [%1], 16;"
                         :: "r"(d), "l"(s) : "memory");
        }
        asm volatile("cp.async.commit_group;" ::: "memory");
        asm volatile("cp.async.wait_group 0;" ::: "memory");
        __syncthreads();

        #pragma unroll
        for (int ks = 0; ks < 8; ++ks) {
            const int kg = kc * 128 + ks * 16;
            const __nv_bfloat16* r0 = eb + (tg * 16 + g) * EBS + kg + tig * 2;
            const __nv_bfloat16* r1 = r0 + 8 * EBS;
            u32 a[4];
            a[0] = *(const u32*)r0;
            a[1] = *(const u32*)r1;
            a[2] = *(const u32*)(r0 + 8);
            a[3] = *(const u32*)(r1 + 8);
            #pragma unroll
            for (int ni = 0; ni < 8; ++ni) {
                const int ch = cg * 64 + ni * 8 + g;
                const __nv_bfloat16* wr = w2 + ch * 136 + ks * 16 + tig * 2;
                u32 bb[2];
                bb[0] = *(const u32*)wr;
                bb[1] = *(const u32*)(wr + 8);
                mma16816(acc[ni], a, bb);
            }
        }
    }

    __syncthreads();
    #pragma unroll
    for (int ni = 0; ni < 8; ++ni) {
        const int ch = cg * 64 + ni * 8 + tig * 2;
        const int tt = tg * 16 + g;
        D_s[ch * 65 + tt]           = acc[ni][0];
        D_s[(ch + 1) * 65 + tt]     = acc[ni][1];
        D_s[ch * 65 + tt + 8]       = acc[ni][2];
        D_s[(ch + 1) * 65 + tt + 8] = acc[ni][3];
    }
    __syncthreads();

    #pragma unroll 1
    for (int i = tid; i < NCLS * ET; i += 512) {
        int ch = i >> 6, t = i & 63;
        out[(b * NCLS + ch) * TD + t0 + t] = D_s[ch * 65 + t];
    }
}

// ---------------- launch ----------------
extern "C" void kernel_launch(void* const* d_in, const int* in_sizes, int n_in,
                              void* d_out, int out_size) {
    const float* x       = (const float*)d_in[0];
    const float* h       = (const float*)d_in[1];
    const float* start_w = (const float*)d_in[2];
    const float* dil_w   = (const float*)d_in[3];
    const float* f_w     = (const float*)d_in[4];
    const float* g_w     = (const float*)d_in[5];
    const float* cf_w    = (const float*)d_in[6];
    const float* cg_w    = (const float*)d_in[7];
    const float* out_w   = (const float*)d_in[8];
    const float* e1_w    = (const float*)d_in[9];
    const float* e2_w    = (const float*)d_in[10];
    float* out = (float*)d_out;

    cudaFuncSetAttribute(wn_cond, cudaFuncAttributeMaxDynamicSharedMemorySize, CSM2);
    cudaFuncSetAttribute(wn_main, cudaFuncAttributeMaxDynamicSharedMemorySize, SM1B);
    cudaFuncSetAttribute(wn_end,  cudaFuncAttributeMaxDynamicSharedMemorySize, CSM3);

    wn_pack<<<256, 256>>>(dil_w, f_w, g_w, cf_w, cg_w, out_w, e1_w, e2_w);
    wn_cond<<<512, 256, CSM2>>>(h);
    wn_main<<<dim3(NTILES, BD), NT1, SM1B>>>(x, start_w);
    wn_end<<<dim3(TD / ET, BD), 512, CSM3>>>(out);
}